// round 7
// baseline (speedup 1.0000x reference)
#include <cuda_runtime.h>
#include <cuda_bf16.h>
#include <math.h>
#include <stdint.h>

#define BB 2
#define TT 2048
#define DD 1024
#define HH 16
#define DH 64
#define MM (BB*TT)

/* ---- gemm geometry: CTA 128x256, warp 64x64, k-chunk 32, 3-stage ring ---- */
#define GST 40               /* smem row stride in bf16 (80B, ldmatrix-safe) */
#define GTA (128*GST)        /* A tile rows (one of hi/lo) */
#define GTB (256*GST)        /* B tile rows (one of hi/lo) */
#define GSTAGE (2*GTA + 2*GTB)
#define NSTG 3
#define NCH  32              /* 1024 / 32 */
#define GEMM_SMEM (NSTG*GSTAGE*2)   /* 184320 B */

#define KST 72               /* attn smem row stride (bf16) */
#define ATILE (64*KST)
#define STAGE (6*ATILE)

// ---------------- scratch (device globals) ----------------------------------
__device__ float g_p5[5*MM*DD];
__device__ __nv_bfloat16 g_xh [MM*DD], g_xl [MM*DD];
__device__ __nv_bfloat16 g_zh [MM*DD], g_zl [MM*DD];
__device__ __nv_bfloat16 g_w6h[6*DD*DD], g_w6l[6*DD*DD];
__device__ __nv_bfloat16 g_qh [MM*DD], g_ql [MM*DD];
__device__ __nv_bfloat16 g_q2h[MM*DD], g_q2l[MM*DD];
__device__ __nv_bfloat16 g_kh [MM*DD], g_kl [MM*DD];
__device__ __nv_bfloat16 g_k2h[MM*DD], g_k2l[MM*DD];
__device__ __nv_bfloat16 g_vh [MM*DD], g_vl [MM*DD];

// ---------------------------------------------------------------------------
__device__ __forceinline__ uint32_t saddr(const void* p) {
    return (uint32_t)__cvta_generic_to_shared(p);
}
__device__ __forceinline__ void ldmat_x4(uint32_t (&r)[4], uint32_t a) {
    asm volatile("ldmatrix.sync.aligned.m8n8.x4.shared.b16 {%0,%1,%2,%3}, [%4];"
                 : "=r"(r[0]), "=r"(r[1]), "=r"(r[2]), "=r"(r[3]) : "r"(a));
}
__device__ __forceinline__ void mma16816(float (&d)[4], const uint32_t (&a)[4],
                                         uint32_t b0, uint32_t b1) {
    asm volatile(
        "mma.sync.aligned.m16n8k16.row.col.f32.bf16.bf16.f32 "
        "{%0,%1,%2,%3}, {%4,%5,%6,%7}, {%8,%9}, {%0,%1,%2,%3};"
        : "+f"(d[0]), "+f"(d[1]), "+f"(d[2]), "+f"(d[3])
        : "r"(a[0]), "r"(a[1]), "r"(a[2]), "r"(a[3]), "r"(b0), "r"(b1));
}
__device__ __forceinline__ void cpa16(void* dst, const void* src) {
    asm volatile("cp.async.cg.shared.global [%0], [%1], 16;"
                 :: "r"(saddr(dst)), "l"(src));
}
__device__ __forceinline__ void cpa_commit() { asm volatile("cp.async.commit_group;"); }
__device__ __forceinline__ void cpa_wait0()  { asm volatile("cp.async.wait_group 0;"); }
__device__ __forceinline__ void cpa_wait1()  { asm volatile("cp.async.wait_group 1;"); }

__device__ __forceinline__ void fsplit(float x, unsigned short& h, unsigned short& l) {
    __nv_bfloat16 hb = __float2bfloat16_rn(x);
    __nv_bfloat16 lb = __float2bfloat16_rn(x - __bfloat162float(hb));
    h = __bfloat16_as_ushort(hb);
    l = __bfloat16_as_ushort(lb);
}

// ---------------------------------------------------------------------------
// splits
// ---------------------------------------------------------------------------
__global__ void split_f32(const float* __restrict__ in,
                          __nv_bfloat16* __restrict__ hi,
                          __nv_bfloat16* __restrict__ lo) {
    const size_t i = ((size_t)blockIdx.x * 256 + threadIdx.x) * 4;
    float4 v = *(const float4*)(in + i);
    float f[4] = {v.x, v.y, v.z, v.w};
    unsigned short h[4], l[4];
#pragma unroll
    for (int e = 0; e < 4; e++) fsplit(f[e], h[e], l[e]);
    *(uint2*)(hi + i) = make_uint2((uint32_t)h[1] << 16 | h[0],
                                   (uint32_t)h[3] << 16 | h[2]);
    *(uint2*)(lo + i) = make_uint2((uint32_t)l[1] << 16 | l[0],
                                   (uint32_t)l[3] << 16 | l[2]);
}

__global__ void split_w6(const float* __restrict__ w0, const float* __restrict__ w1,
                         const float* __restrict__ w2, const float* __restrict__ w3,
                         const float* __restrict__ w4, const float* __restrict__ w5,
                         __nv_bfloat16* __restrict__ hi, __nv_bfloat16* __restrict__ lo) {
    const float* src[6] = {w0, w1, w2, w3, w4, w5};
    const float* in = src[blockIdx.y];
    const size_t off = (size_t)blockIdx.y * DD * DD;
    const size_t i = ((size_t)blockIdx.x * 256 + threadIdx.x) * 4;
    float4 v = *(const float4*)(in + i);
    float f[4] = {v.x, v.y, v.z, v.w};
    unsigned short h[4], l[4];
#pragma unroll
    for (int e = 0; e < 4; e++) fsplit(f[e], h[e], l[e]);
    *(uint2*)(hi + off + i) = make_uint2((uint32_t)h[1] << 16 | h[0],
                                         (uint32_t)h[3] << 16 | h[2]);
    *(uint2*)(lo + off + i) = make_uint2((uint32_t)l[1] << 16 | l[0],
                                         (uint32_t)l[3] << 16 | l[2]);
}

// ---------------------------------------------------------------------------
// C[M,N] = A[M,K] @ W[N,K]^T, bf16 hi/lo 3-term mma.sync.
// CTA 128x256, 8 warps (64x64 each), k-chunk 32, 3-stage cp.async ring.
// ---------------------------------------------------------------------------
__global__ void __launch_bounds__(256, 1) gemm_bf16(
        const __nv_bfloat16* __restrict__ Ah, const __nv_bfloat16* __restrict__ Al,
        const __nv_bfloat16* __restrict__ Wh, const __nv_bfloat16* __restrict__ Wl,
        float* __restrict__ C) {
    extern __shared__ __nv_bfloat16 sg[];
    const int zi = blockIdx.z;
    Wh += (size_t)zi * DD * DD;
    Wl += (size_t)zi * DD * DD;
    C  += (size_t)zi * MM * DD;

    const int tid  = threadIdx.x;
    const int wid  = tid >> 5;
    const int lane = tid & 31;
    const int m0 = blockIdx.y * 128;
    const int n0 = blockIdx.x * 256;
    const int wm = wid & 1;        // 2 m-slabs of 64
    const int wn = wid >> 1;       // 4 n-slabs of 64

    auto load_chunk = [&](int c) {
        __nv_bfloat16* base = sg + (c % NSTG) * GSTAGE;
        const int k0 = c * 32;
        // A: 128 rows x 32k (hi+lo)
#pragma unroll 2
        for (int i = tid; i < 512; i += 256) {
            const int r  = i >> 2;
            const int ck = (i & 3) * 8;
            const int so = r * GST + ck;
            cpa16(base + so,       Ah + (size_t)(m0 + r) * DD + k0 + ck);
            cpa16(base + GTA + so, Al + (size_t)(m0 + r) * DD + k0 + ck);
        }
        // B: 256 rows x 32k (hi+lo)
        __nv_bfloat16* bb = base + 2 * GTA;
#pragma unroll 4
        for (int i = tid; i < 1024; i += 256) {
            const int r  = i >> 2;
            const int ck = (i & 3) * 8;
            const int so = r * GST + ck;
            cpa16(bb + so,       Wh + (size_t)(n0 + r) * DD + k0 + ck);
            cpa16(bb + GTB + so, Wl + (size_t)(n0 + r) * DD + k0 + ck);
        }
        cpa_commit();
    };

    float acc[4][8][4];
#pragma unroll
    for (int i = 0; i < 4; i++)
#pragma unroll
        for (int j = 0; j < 8; j++)
#pragma unroll
            for (int c = 0; c < 4; c++) acc[i][j][c] = 0.0f;

    load_chunk(0);
    load_chunk(1);

    for (int ch = 0; ch < NCH; ch++) {
        if (ch + 1 < NCH) cpa_wait1();
        else              cpa_wait0();
        __syncthreads();
        if (ch + 2 < NCH) load_chunk(ch + 2);

        const __nv_bfloat16* cur = sg + (ch % NSTG) * GSTAGE;
        const __nv_bfloat16* Ahi = cur;
        const __nv_bfloat16* Alo = cur + GTA;
        const __nv_bfloat16* Bhi = cur + 2 * GTA;
        const __nv_bfloat16* Blo = cur + 2 * GTA + GTB;

#pragma unroll
        for (int kk = 0; kk < 2; kk++) {
            uint32_t ahi[4][4], alo[4][4], bhi[4][4], blo[4][4];
            const int ar = wm * 64 + (lane & 15);
            const int ak = kk * 16 + (lane >> 4) * 8;
#pragma unroll
            for (int mi = 0; mi < 4; mi++) {
                ldmat_x4(ahi[mi], saddr(Ahi + (ar + mi * 16) * GST + ak));
                ldmat_x4(alo[mi], saddr(Alo + (ar + mi * 16) * GST + ak));
            }
            const int br = wn * 64 + ((lane >> 4) & 1) * 8 + (lane & 7);
            const int bk = kk * 16 + ((lane >> 3) & 1) * 8;
#pragma unroll
            for (int p = 0; p < 4; p++) {
                ldmat_x4(bhi[p], saddr(Bhi + (br + p * 16) * GST + bk));
                ldmat_x4(blo[p], saddr(Blo + (br + p * 16) * GST + bk));
            }
#pragma unroll
            for (int mi = 0; mi < 4; mi++)
#pragma unroll
                for (int ni = 0; ni < 8; ni++) {
                    const uint32_t* bh = &bhi[ni >> 1][(ni & 1) * 2];
                    const uint32_t* bl = &blo[ni >> 1][(ni & 1) * 2];
                    mma16816(acc[mi][ni], ahi[mi], bh[0], bh[1]);
                    mma16816(acc[mi][ni], ahi[mi], bl[0], bl[1]);
                    mma16816(acc[mi][ni], alo[mi], bh[0], bh[1]);
                }
        }
    }

#pragma unroll
    for (int mi = 0; mi < 4; mi++)
#pragma unroll
        for (int ni = 0; ni < 8; ni++) {
            const int r0 = m0 + wm * 64 + mi * 16 + (lane >> 2);
            const int c0 = n0 + wn * 64 + ni * 8 + (lane & 3) * 2;
            *(float2*)(C + (size_t)r0 * 1024 + c0) =
                make_float2(acc[mi][ni][0], acc[mi][ni][1]);
            *(float2*)(C + (size_t)(r0 + 8) * 1024 + c0) =
                make_float2(acc[mi][ni][2], acc[mi][ni][3]);
        }
}

// ---------------------------------------------------------------------------
// RoPE + split to bf16 hi/lo
// ---------------------------------------------------------------------------
__global__ void rope_split(const float* __restrict__ p5,
                           __nv_bfloat16* __restrict__ qh,  __nv_bfloat16* __restrict__ ql,
                           __nv_bfloat16* __restrict__ kh,  __nv_bfloat16* __restrict__ kl,
                           __nv_bfloat16* __restrict__ q2h, __nv_bfloat16* __restrict__ q2l,
                           __nv_bfloat16* __restrict__ k2h, __nv_bfloat16* __restrict__ k2l,
                           __nv_bfloat16* __restrict__ vh,  __nv_bfloat16* __restrict__ vl) {
    const int idx = blockIdx.x * blockDim.x + threadIdx.x;
    const int i = idx & 31;
    const int h = (idx >> 5) & (HH - 1);
    const int t = (idx >> 9) & (TT - 1);
    const int b = idx >> 20;

    const float inv_freq = powf(10000.0f, -(float)i * (1.0f / 32.0f));
    float c, s;
    sincosf((float)t * inv_freq, &s, &c);

    const size_t base = ((size_t)(b * TT + t)) * DD + h * DH + i;

    __nv_bfloat16* oh[4] = {qh, kh, q2h, k2h};
    __nv_bfloat16* ol[4] = {ql, kl, q2l, k2l};
#pragma unroll
    for (int a = 0; a < 4; a++) {
        const float* in = p5 + (size_t)a * MM * DD;
        float x1 = in[base];
        float x2 = in[base + 32];
        float y1 = fmaf(x1, c, x2 * s);
        float y2 = fmaf(-x1, s, x2 * c);
        unsigned short hh, lll;
        fsplit(y1, hh, lll);
        oh[a][base]      = __ushort_as_bfloat16(hh);
        ol[a][base]      = __ushort_as_bfloat16(lll);
        fsplit(y2, hh, lll);
        oh[a][base + 32] = __ushort_as_bfloat16(hh);
        ol[a][base + 32] = __ushort_as_bfloat16(lll);
    }
    {
        const float* vv = p5 + (size_t)4 * MM * DD;
        unsigned short hh, lll;
        fsplit(vv[base], hh, lll);
        vh[base]      = __ushort_as_bfloat16(hh);
        vl[base]      = __ushort_as_bfloat16(lll);
        fsplit(vv[base + 32], hh, lll);
        vh[base + 32] = __ushort_as_bfloat16(hh);
        vl[base + 32] = __ushort_as_bfloat16(lll);
    }
}

// ---------------------------------------------------------------------------
// Tensor-core causal bilinear attention; epilogue writes z as bf16 hi/lo.
// ---------------------------------------------------------------------------
__global__ void __launch_bounds__(256, 1) attn_mma(
        const __nv_bfloat16* __restrict__ qh,  const __nv_bfloat16* __restrict__ ql,
        const __nv_bfloat16* __restrict__ q2h, const __nv_bfloat16* __restrict__ q2l,
        const __nv_bfloat16* __restrict__ kh,  const __nv_bfloat16* __restrict__ kl,
        const __nv_bfloat16* __restrict__ k2h, const __nv_bfloat16* __restrict__ k2l,
        const __nv_bfloat16* __restrict__ vh,  const __nv_bfloat16* __restrict__ vl,
        __nv_bfloat16* __restrict__ zh, __nv_bfloat16* __restrict__ zl) {
    extern __shared__ __nv_bfloat16 sb2[];
    const int tid  = threadIdx.x;
    const int lane = tid & 31;
    const int w    = tid >> 5;
    const int qb = (int)gridDim.x - 1 - (int)blockIdx.x;
    const int q0 = qb * 128;
    const int b  = blockIdx.y >> 4;
    const int h  = blockIdx.y & 15;
    const size_t bh_off = (size_t)b * TT * DD + h * DH;

    {
        const __nv_bfloat16* src[4] = {qh, ql, q2h, q2l};
#pragma unroll
        for (int a = 0; a < 4; a++) {
            __nv_bfloat16* dst = sb2 + a * 128 * KST;
            for (int i = tid; i < 1024; i += 256) {
                const int r = i >> 3, ck = (i & 7) * 8;
                cpa16(dst + r * KST + ck, src[a] + bh_off + (size_t)(q0 + r) * DD + ck);
            }
        }
        cpa_commit();
        cpa_wait0();
        __syncthreads();
    }

    uint32_t fqh[4][4], fql[4][4], fq2h[4][4], fq2l[4][4];
    {
        const int ar = w * 16 + (lane & 15);
        const int ak = (lane >> 4) * 8;
#pragma unroll
        for (int kf = 0; kf < 4; kf++) {
            ldmat_x4(fqh [kf], saddr(sb2 + 0 * 128 * KST + ar * KST + kf * 16 + ak));
            ldmat_x4(fql [kf], saddr(sb2 + 1 * 128 * KST + ar * KST + kf * 16 + ak));
            ldmat_x4(fq2h[kf], saddr(sb2 + 2 * 128 * KST + ar * KST + kf * 16 + ak));
            ldmat_x4(fq2l[kf], saddr(sb2 + 3 * 128 * KST + ar * KST + kf * 16 + ak));
        }
    }
    __syncthreads();

    float zacc[8][4];
#pragma unroll
    for (int i = 0; i < 8; i++)
#pragma unroll
        for (int j = 0; j < 4; j++) zacc[i][j] = 0.0f;

    const int nkv = 2 * qb + 2;
    const int br = (lane & 7) + ((lane >> 4) & 1) * 8;
    const int bk = ((lane >> 3) & 1) * 8;
    const float invd2 = 1.0f / ((float)DH * (float)DH);

    auto load_tile = [&](int kj, int buf) {
        __nv_bfloat16* base = sb2 + buf * STAGE;
        const int kv0 = kj * 64;
        const __nv_bfloat16* src[4] = {kh, kl, k2h, k2l};
#pragma unroll
        for (int a = 0; a < 4; a++) {
            __nv_bfloat16* dst = base + a * ATILE;
            for (int i = tid; i < 512; i += 256) {
                const int r = i >> 3, ck = (i & 7) * 8;
                cpa16(dst + r * KST + ck, src[a] + bh_off + (size_t)(kv0 + r) * DD + ck);
            }
        }
        {
            const int r  = tid & 63;
            const int dg = (tid >> 6) * 16;
            const __nv_bfloat16* s1p = vh + bh_off + (size_t)(kv0 + r) * DD + dg;
            const __nv_bfloat16* s2p = vl + bh_off + (size_t)(kv0 + r) * DD + dg;
            unsigned short t1[16], t2[16];
            *(uint4*)t1       = *(const uint4*)s1p;
            *(uint4*)(t1 + 8) = *(const uint4*)(s1p + 8);
            *(uint4*)t2       = *(const uint4*)s2p;
            *(uint4*)(t2 + 8) = *(const uint4*)(s2p + 8);
            unsigned short* dh = (unsigned short*)(base + 4 * ATILE);
            unsigned short* dl = (unsigned short*)(base + 5 * ATILE);
#pragma unroll
            for (int j = 0; j < 16; j++) {
                dh[(dg + j) * KST + r] = t1[j];
                dl[(dg + j) * KST + r] = t2[j];
            }
        }
    };

    load_tile(0, 0);
    cpa_commit();

    for (int kj = 0; kj < nkv; kj++) {
        cpa_wait0();
        __syncthreads();
        if (kj + 1 < nkv) {
            load_tile(kj + 1, (kj + 1) & 1);
            cpa_commit();
        }

        const __nv_bfloat16* base = sb2 + (kj & 1) * STAGE;
        const int kv0 = kj * 64;
        const bool masked = (kv0 >= q0);

        uint32_t ph[8][2], pl[8][2];
#pragma unroll
        for (int g = 0; g < 4; g++) {
            float s1f[2][4], s2f[2][4];
#pragma unroll
            for (int p = 0; p < 2; p++)
#pragma unroll
                for (int e = 0; e < 4; e++) { s1f[p][e] = 0.0f; s2f[p][e] = 0.0f; }

#pragma unroll
            for (int kf = 0; kf < 4; kf++) {
                uint32_t bh_[4], bl_[4];
                const int off = (g * 16 + br) * KST + kf * 16 + bk;
                ldmat_x4(bh_, saddr(base + 0 * ATILE + off));
                ldmat_x4(bl_, saddr(base + 1 * ATILE + off));
#pragma unroll
                for (int p = 0; p < 2; p++) {
                    mma16816(s1f[p], fqh[kf], bh_[p*2], bh_[p*2+1]);
                    mma16816(s1f[p], fqh[kf], bl_[p*2], bl_[p*2+1]);
                    mma16816(s1f[p], fql[kf], bh_[p*2], bh_[p*2+1]);
                }
                ldmat_x4(bh_, saddr(base + 2 * ATILE + off));
                ldmat_x4(bl_, saddr(base + 3 * ATILE + off));
#pragma unroll
                for (int p = 0; p < 2; p++) {
                    mma16816(s2f[p], fq2h[kf], bh_[p*2], bh_[p*2+1]);
                    mma16816(s2f[p], fq2h[kf], bl_[p*2], bl_[p*2+1]);
                    mma16816(s2f[p], fq2l[kf], bh_[p*2], bh_[p*2+1]);
                }
            }
#pragma unroll
            for (int p = 0; p < 2; p++) {
                const int j = g * 2 + p;
                float pr[4];
#pragma unroll
                for (int e = 0; e < 4; e++) pr[e] = s1f[p][e] * s2f[p][e] * invd2;
                if (masked) {
                    const int qr = q0 + w * 16 + (lane >> 2);
                    const int kc = kv0 + j * 8 + (lane & 3) * 2;
                    if (kc     > qr)     pr[0] = 0.0f;
                    if (kc + 1 > qr)     pr[1] = 0.0f;
                    if (kc     > qr + 8) pr[2] = 0.0f;
                    if (kc + 1 > qr + 8) pr[3] = 0.0f;
                }
                unsigned short hh[4], ll[4];
#pragma unroll
                for (int e = 0; e < 4; e++) fsplit(pr[e], hh[e], ll[e]);
                ph[j][0] = (uint32_t)hh[1] << 16 | hh[0];
                ph[j][1] = (uint32_t)hh[3] << 16 | hh[2];
                pl[j][0] = (uint32_t)ll[1] << 16 | ll[0];
                pl[j][1] = (uint32_t)ll[3] << 16 | ll[2];
            }
        }

#pragma unroll
        for (int f = 0; f < 4; f++) {
            uint32_t ah[4] = {ph[2*f][0], ph[2*f][1], ph[2*f+1][0], ph[2*f+1][1]};
            uint32_t al[4] = {pl[2*f][0], pl[2*f][1], pl[2*f+1][0], pl[2*f+1][1]};
#pragma unroll
            for (int gd = 0; gd < 4; gd++) {
                uint32_t vh_[4], vl_[4];
                const int off = (gd * 16 + br) * KST + f * 16 + bk;
                ldmat_x4(vh_, saddr(base + 4 * ATILE + off));
                ldmat_x4(vl_, saddr(base + 5 * ATILE + off));
#pragma unroll
                for (int p = 0; p < 2; p++) {
                    mma16816(zacc[gd*2+p], ah, vh_[p*2], vh_[p*2+1]);
                    mma16816(zacc[gd*2+p], ah, vl_[p*2], vl_[p*2+1]);
                    mma16816(zacc[gd*2+p], al, vh_[p*2], vh_[p*2+1]);
                }
            }
        }
    }

    {
        const int r = q0 + w * 16 + (lane >> 2);
        const int c = (lane & 3) * 2;
#pragma unroll
        for (int nd = 0; nd < 8; nd++) {
            unsigned short h0, l0, h1, l1;
#pragma unroll
            for (int half = 0; half < 2; half++) {
                fsplit(zacc[nd][half * 2 + 0], h0, l0);
                fsplit(zacc[nd][half * 2 + 1], h1, l1);
                const size_t off = bh_off + (size_t)(r + half * 8) * DD + nd * 8 + c;
                *(uint32_t*)(zh + off) = (uint32_t)h1 << 16 | h0;
                *(uint32_t*)(zl + off) = (uint32_t)l1 << 16 | l0;
            }
        }
    }
}

// ---------------------------------------------------------------------------
extern "C" void kernel_launch(void* const* d_in, const int* in_sizes, int n_in,
                              void* d_out, int out_size) {
    const float* x     = (const float*)d_in[0];
    const float* Wq    = (const float*)d_in[1];
    const float* Wk    = (const float*)d_in[2];
    const float* Wq2   = (const float*)d_in[3];
    const float* Wk2   = (const float*)d_in[4];
    const float* Wv    = (const float*)d_in[5];
    const float* Wproj = (const float*)d_in[6];
    float* out = (float*)d_out;

    float* p5;
    cudaGetSymbolAddress((void**)&p5, g_p5);

    __nv_bfloat16 *xh, *xl, *zh, *zl, *w6h, *w6l;
    cudaGetSymbolAddress((void**)&xh,  g_xh);  cudaGetSymbolAddress((void**)&xl,  g_xl);
    cudaGetSymbolAddress((void**)&zh,  g_zh);  cudaGetSymbolAddress((void**)&zl,  g_zl);
    cudaGetSymbolAddress((void**)&w6h, g_w6h); cudaGetSymbolAddress((void**)&w6l, g_w6l);

    __nv_bfloat16 *qh, *ql, *q2h, *q2l, *kh, *kl, *k2h, *k2l, *vh, *vl;
    cudaGetSymbolAddress((void**)&qh,  g_qh);  cudaGetSymbolAddress((void**)&ql,  g_ql);
    cudaGetSymbolAddress((void**)&q2h, g_q2h); cudaGetSymbolAddress((void**)&q2l, g_q2l);
    cudaGetSymbolAddress((void**)&kh,  g_kh);  cudaGetSymbolAddress((void**)&kl,  g_kl);
    cudaGetSymbolAddress((void**)&k2h, g_k2h); cudaGetSymbolAddress((void**)&k2l, g_k2l);
    cudaGetSymbolAddress((void**)&vh,  g_vh);  cudaGetSymbolAddress((void**)&vl,  g_vl);

    cudaFuncSetAttribute(gemm_bf16,
                         cudaFuncAttributeMaxDynamicSharedMemorySize, GEMM_SMEM);

    // 1) split inputs
    split_f32<<<MM * DD / 1024, 256>>>(x, xh, xl);
    split_w6<<<dim3(DD * DD / 1024, 6), 256>>>(Wq, Wk, Wq2, Wk2, Wv, Wproj, w6h, w6l);

    // 2) five fused projections (CTA 128x256)
    gemm_bf16<<<dim3(DD / 256, MM / 128, 5), 256, GEMM_SMEM>>>(xh, xl, w6h, w6l, p5);

    // 3) rope + split
    rope_split<<<(BB * TT * HH * 32) / 256, 256>>>(p5, qh, ql, kh, kl,
                                                   q2h, q2l, k2h, k2l, vh, vl);

    // 4) attention (writes zh/zl directly)
    const int attn_smem = 2 * STAGE * (int)sizeof(__nv_bfloat16);
    cudaFuncSetAttribute(attn_mma,
                         cudaFuncAttributeMaxDynamicSharedMemorySize, attn_smem);
    attn_mma<<<dim3(TT / 128, BB * HH), 256, attn_smem>>>(
        qh, ql, q2h, q2l, kh, kl, k2h, k2l, vh, vl, zh, zl);

    // 5) output projection
    gemm_bf16<<<dim3(DD / 256, MM / 128, 1), 256, GEMM_SMEM>>>(
        zh, zl, w6h + (size_t)5 * DD * DD, w6l + (size_t)5 * DD * DD, out);
}

// round 8
// speedup vs baseline: 1.0340x; 1.0340x over previous
#include <cuda_runtime.h>
#include <cuda_bf16.h>
#include <math.h>
#include <stdint.h>

#define BB 2
#define TT 2048
#define DD 1024
#define HH 16
#define DH 64
#define MM (BB*TT)

/* ---- gemm geometry: CTA 128x128, 16 warps (32x32 each), k-chunk 64 ---- */
#define GST 72              /* smem row stride in bf16 (144B, conflict-free) */
#define GTILE (128*GST)     /* one 128x64 operand tile */
#define GSTAGE (4*GTILE)    /* Ah,Al,Wh,Wl per stage */
#define NSTG 3
#define NCH  16             /* 1024 / 64 */
#define GEMM_SMEM (NSTG*GSTAGE*2)   /* 221184 B */

#define KST 72              /* attn smem row stride (bf16) */
#define ATILE (64*KST)
#define STAGE (6*ATILE)

// ---------------- scratch (device globals) ----------------------------------
__device__ float g_p5[5*MM*DD];
__device__ __nv_bfloat16 g_xh [MM*DD], g_xl [MM*DD];
__device__ __nv_bfloat16 g_zh [MM*DD], g_zl [MM*DD];
__device__ __nv_bfloat16 g_w6h[6*DD*DD], g_w6l[6*DD*DD];
__device__ __nv_bfloat16 g_qh [MM*DD], g_ql [MM*DD];
__device__ __nv_bfloat16 g_q2h[MM*DD], g_q2l[MM*DD];
__device__ __nv_bfloat16 g_kh [MM*DD], g_kl [MM*DD];
__device__ __nv_bfloat16 g_k2h[MM*DD], g_k2l[MM*DD];
__device__ __nv_bfloat16 g_vh [MM*DD], g_vl [MM*DD];

// ---------------------------------------------------------------------------
__device__ __forceinline__ uint32_t saddr(const void* p) {
    return (uint32_t)__cvta_generic_to_shared(p);
}
__device__ __forceinline__ void ldmat_x4(uint32_t (&r)[4], uint32_t a) {
    asm volatile("ldmatrix.sync.aligned.m8n8.x4.shared.b16 {%0,%1,%2,%3}, [%4];"
                 : "=r"(r[0]), "=r"(r[1]), "=r"(r[2]), "=r"(r[3]) : "r"(a));
}
__device__ __forceinline__ void mma16816(float (&d)[4], const uint32_t (&a)[4],
                                         uint32_t b0, uint32_t b1) {
    asm volatile(
        "mma.sync.aligned.m16n8k16.row.col.f32.bf16.bf16.f32 "
        "{%0,%1,%2,%3}, {%4,%5,%6,%7}, {%8,%9}, {%0,%1,%2,%3};"
        : "+f"(d[0]), "+f"(d[1]), "+f"(d[2]), "+f"(d[3])
        : "r"(a[0]), "r"(a[1]), "r"(a[2]), "r"(a[3]), "r"(b0), "r"(b1));
}
__device__ __forceinline__ void cpa16(void* dst, const void* src) {
    asm volatile("cp.async.cg.shared.global [%0], [%1], 16;"
                 :: "r"(saddr(dst)), "l"(src));
}
__device__ __forceinline__ void cpa_commit() { asm volatile("cp.async.commit_group;"); }
__device__ __forceinline__ void cpa_wait0()  { asm volatile("cp.async.wait_group 0;"); }
__device__ __forceinline__ void cpa_wait1()  { asm volatile("cp.async.wait_group 1;"); }

__device__ __forceinline__ void fsplit(float x, unsigned short& h, unsigned short& l) {
    __nv_bfloat16 hb = __float2bfloat16_rn(x);
    __nv_bfloat16 lb = __float2bfloat16_rn(x - __bfloat162float(hb));
    h = __bfloat16_as_ushort(hb);
    l = __bfloat16_as_ushort(lb);
}

// ---------------------------------------------------------------------------
// splits
// ---------------------------------------------------------------------------
__global__ void split_f32(const float* __restrict__ in,
                          __nv_bfloat16* __restrict__ hi,
                          __nv_bfloat16* __restrict__ lo) {
    const size_t i = ((size_t)blockIdx.x * 256 + threadIdx.x) * 4;
    float4 v = *(const float4*)(in + i);
    float f[4] = {v.x, v.y, v.z, v.w};
    unsigned short h[4], l[4];
#pragma unroll
    for (int e = 0; e < 4; e++) fsplit(f[e], h[e], l[e]);
    *(uint2*)(hi + i) = make_uint2((uint32_t)h[1] << 16 | h[0],
                                   (uint32_t)h[3] << 16 | h[2]);
    *(uint2*)(lo + i) = make_uint2((uint32_t)l[1] << 16 | l[0],
                                   (uint32_t)l[3] << 16 | l[2]);
}

__global__ void split_w6(const float* __restrict__ w0, const float* __restrict__ w1,
                         const float* __restrict__ w2, const float* __restrict__ w3,
                         const float* __restrict__ w4, const float* __restrict__ w5,
                         __nv_bfloat16* __restrict__ hi, __nv_bfloat16* __restrict__ lo) {
    const float* src[6] = {w0, w1, w2, w3, w4, w5};
    const float* in = src[blockIdx.y];
    const size_t off = (size_t)blockIdx.y * DD * DD;
    const size_t i = ((size_t)blockIdx.x * 256 + threadIdx.x) * 4;
    float4 v = *(const float4*)(in + i);
    float f[4] = {v.x, v.y, v.z, v.w};
    unsigned short h[4], l[4];
#pragma unroll
    for (int e = 0; e < 4; e++) fsplit(f[e], h[e], l[e]);
    *(uint2*)(hi + off + i) = make_uint2((uint32_t)h[1] << 16 | h[0],
                                         (uint32_t)h[3] << 16 | h[2]);
    *(uint2*)(lo + off + i) = make_uint2((uint32_t)l[1] << 16 | l[0],
                                         (uint32_t)l[3] << 16 | l[2]);
}

// ---------------------------------------------------------------------------
// C[M,N] = A[M,K] @ W[N,K]^T, bf16 hi/lo 3-term mma.sync.
// CTA 128x128, 16 warps (32x32 each), k-chunk 64, 3-stage cp.async ring.
// ---------------------------------------------------------------------------
__global__ void __launch_bounds__(512, 1) gemm_bf16(
        const __nv_bfloat16* __restrict__ Ah, const __nv_bfloat16* __restrict__ Al,
        const __nv_bfloat16* __restrict__ Wh, const __nv_bfloat16* __restrict__ Wl,
        float* __restrict__ C) {
    extern __shared__ __nv_bfloat16 sg[];
    const int zi = blockIdx.z;
    Wh += (size_t)zi * DD * DD;
    Wl += (size_t)zi * DD * DD;
    C  += (size_t)zi * MM * DD;

    const int tid  = threadIdx.x;
    const int wid  = tid >> 5;
    const int lane = tid & 31;
    const int m0 = blockIdx.y * 128;
    const int n0 = blockIdx.x * 128;
    const int wm = wid & 3;        // 4 m-slabs of 32
    const int wn = wid >> 2;       // 4 n-slabs of 32

    auto load_chunk = [&](int c) {
        __nv_bfloat16* base = sg + (c % NSTG) * GSTAGE;
        const int k0 = c * 64;
#pragma unroll 2
        for (int i = tid; i < 1024; i += 512) {
            const int r  = i >> 3;
            const int ck = (i & 7) * 8;
            const int so = r * GST + ck;
            cpa16(base + 0 * GTILE + so, Ah + (size_t)(m0 + r) * DD + k0 + ck);
            cpa16(base + 1 * GTILE + so, Al + (size_t)(m0 + r) * DD + k0 + ck);
            cpa16(base + 2 * GTILE + so, Wh + (size_t)(n0 + r) * DD + k0 + ck);
            cpa16(base + 3 * GTILE + so, Wl + (size_t)(n0 + r) * DD + k0 + ck);
        }
        cpa_commit();
    };

    float acc[2][4][4];
#pragma unroll
    for (int i = 0; i < 2; i++)
#pragma unroll
        for (int j = 0; j < 4; j++)
#pragma unroll
            for (int c = 0; c < 4; c++) acc[i][j][c] = 0.0f;

    load_chunk(0);
    load_chunk(1);

    for (int ch = 0; ch < NCH; ch++) {
        if (ch + 1 < NCH) cpa_wait1();
        else              cpa_wait0();
        __syncthreads();
        if (ch + 2 < NCH) load_chunk(ch + 2);

        const __nv_bfloat16* cur = sg + (ch % NSTG) * GSTAGE;
        const __nv_bfloat16* Ahi = cur;
        const __nv_bfloat16* Alo = cur + GTILE;
        const __nv_bfloat16* Bhi = cur + 2 * GTILE;
        const __nv_bfloat16* Blo = cur + 3 * GTILE;

#pragma unroll
        for (int kk = 0; kk < 4; kk++) {
            uint32_t ahi[2][4], alo[2][4], bhi[2][4], blo[2][4];
            const int ar = wm * 32 + (lane & 15);
            const int ak = kk * 16 + (lane >> 4) * 8;
#pragma unroll
            for (int mi = 0; mi < 2; mi++) {
                ldmat_x4(ahi[mi], saddr(Ahi + (ar + mi * 16) * GST + ak));
                ldmat_x4(alo[mi], saddr(Alo + (ar + mi * 16) * GST + ak));
            }
            const int br = wn * 32 + ((lane >> 4) & 1) * 8 + (lane & 7);
            const int bk = kk * 16 + ((lane >> 3) & 1) * 8;
#pragma unroll
            for (int p = 0; p < 2; p++) {
                ldmat_x4(bhi[p], saddr(Bhi + (br + p * 16) * GST + bk));
                ldmat_x4(blo[p], saddr(Blo + (br + p * 16) * GST + bk));
            }
#pragma unroll
            for (int mi = 0; mi < 2; mi++)
#pragma unroll
                for (int ni = 0; ni < 4; ni++) {
                    const uint32_t* bh = &bhi[ni >> 1][(ni & 1) * 2];
                    const uint32_t* bl = &blo[ni >> 1][(ni & 1) * 2];
                    mma16816(acc[mi][ni], ahi[mi], bh[0], bh[1]);
                    mma16816(acc[mi][ni], ahi[mi], bl[0], bl[1]);
                    mma16816(acc[mi][ni], alo[mi], bh[0], bh[1]);
                }
        }
    }

#pragma unroll
    for (int mi = 0; mi < 2; mi++)
#pragma unroll
        for (int ni = 0; ni < 4; ni++) {
            const int r0 = m0 + wm * 32 + mi * 16 + (lane >> 2);
            const int c0 = n0 + wn * 32 + ni * 8 + (lane & 3) * 2;
            *(float2*)(C + (size_t)r0 * 1024 + c0) =
                make_float2(acc[mi][ni][0], acc[mi][ni][1]);
            *(float2*)(C + (size_t)(r0 + 8) * 1024 + c0) =
                make_float2(acc[mi][ni][2], acc[mi][ni][3]);
        }
}

// ---------------------------------------------------------------------------
// RoPE + split to bf16 hi/lo
// ---------------------------------------------------------------------------
__global__ void rope_split(const float* __restrict__ p5,
                           __nv_bfloat16* __restrict__ qh,  __nv_bfloat16* __restrict__ ql,
                           __nv_bfloat16* __restrict__ kh,  __nv_bfloat16* __restrict__ kl,
                           __nv_bfloat16* __restrict__ q2h, __nv_bfloat16* __restrict__ q2l,
                           __nv_bfloat16* __restrict__ k2h, __nv_bfloat16* __restrict__ k2l,
                           __nv_bfloat16* __restrict__ vh,  __nv_bfloat16* __restrict__ vl) {
    const int idx = blockIdx.x * blockDim.x + threadIdx.x;
    const int i = idx & 31;
    const int h = (idx >> 5) & (HH - 1);
    const int t = (idx >> 9) & (TT - 1);
    const int b = idx >> 20;

    const float inv_freq = powf(10000.0f, -(float)i * (1.0f / 32.0f));
    float c, s;
    sincosf((float)t * inv_freq, &s, &c);

    const size_t base = ((size_t)(b * TT + t)) * DD + h * DH + i;

    __nv_bfloat16* oh[4] = {qh, kh, q2h, k2h};
    __nv_bfloat16* ol[4] = {ql, kl, q2l, k2l};
#pragma unroll
    for (int a = 0; a < 4; a++) {
        const float* in = p5 + (size_t)a * MM * DD;
        float x1 = in[base];
        float x2 = in[base + 32];
        float y1 = fmaf(x1, c, x2 * s);
        float y2 = fmaf(-x1, s, x2 * c);
        unsigned short hh, lll;
        fsplit(y1, hh, lll);
        oh[a][base]      = __ushort_as_bfloat16(hh);
        ol[a][base]      = __ushort_as_bfloat16(lll);
        fsplit(y2, hh, lll);
        oh[a][base + 32] = __ushort_as_bfloat16(hh);
        ol[a][base + 32] = __ushort_as_bfloat16(lll);
    }
    {
        const float* vv = p5 + (size_t)4 * MM * DD;
        unsigned short hh, lll;
        fsplit(vv[base], hh, lll);
        vh[base]      = __ushort_as_bfloat16(hh);
        vl[base]      = __ushort_as_bfloat16(lll);
        fsplit(vv[base + 32], hh, lll);
        vh[base + 32] = __ushort_as_bfloat16(hh);
        vl[base + 32] = __ushort_as_bfloat16(lll);
    }
}

// ---------------------------------------------------------------------------
// Tensor-core causal bilinear attention; epilogue writes z as bf16 hi/lo.
// ---------------------------------------------------------------------------
__global__ void __launch_bounds__(256, 1) attn_mma(
        const __nv_bfloat16* __restrict__ qh,  const __nv_bfloat16* __restrict__ ql,
        const __nv_bfloat16* __restrict__ q2h, const __nv_bfloat16* __restrict__ q2l,
        const __nv_bfloat16* __restrict__ kh,  const __nv_bfloat16* __restrict__ kl,
        const __nv_bfloat16* __restrict__ k2h, const __nv_bfloat16* __restrict__ k2l,
        const __nv_bfloat16* __restrict__ vh,  const __nv_bfloat16* __restrict__ vl,
        __nv_bfloat16* __restrict__ zh, __nv_bfloat16* __restrict__ zl) {
    extern __shared__ __nv_bfloat16 sb2[];
    const int tid  = threadIdx.x;
    const int lane = tid & 31;
    const int w    = tid >> 5;
    const int qb = (int)gridDim.x - 1 - (int)blockIdx.x;
    const int q0 = qb * 128;
    const int b  = blockIdx.y >> 4;
    const int h  = blockIdx.y & 15;
    const size_t bh_off = (size_t)b * TT * DD + h * DH;

    {
        const __nv_bfloat16* src[4] = {qh, ql, q2h, q2l};
#pragma unroll
        for (int a = 0; a < 4; a++) {
            __nv_bfloat16* dst = sb2 + a * 128 * KST;
            for (int i = tid; i < 1024; i += 256) {
                const int r = i >> 3, ck = (i & 7) * 8;
                cpa16(dst + r * KST + ck, src[a] + bh_off + (size_t)(q0 + r) * DD + ck);
            }
        }
        cpa_commit();
        cpa_wait0();
        __syncthreads();
    }

    uint32_t fqh[4][4], fql[4][4], fq2h[4][4], fq2l[4][4];
    {
        const int ar = w * 16 + (lane & 15);
        const int ak = (lane >> 4) * 8;
#pragma unroll
        for (int kf = 0; kf < 4; kf++) {
            ldmat_x4(fqh [kf], saddr(sb2 + 0 * 128 * KST + ar * KST + kf * 16 + ak));
            ldmat_x4(fql [kf], saddr(sb2 + 1 * 128 * KST + ar * KST + kf * 16 + ak));
            ldmat_x4(fq2h[kf], saddr(sb2 + 2 * 128 * KST + ar * KST + kf * 16 + ak));
            ldmat_x4(fq2l[kf], saddr(sb2 + 3 * 128 * KST + ar * KST + kf * 16 + ak));
        }
    }
    __syncthreads();

    float zacc[8][4];
#pragma unroll
    for (int i = 0; i < 8; i++)
#pragma unroll
        for (int j = 0; j < 4; j++) zacc[i][j] = 0.0f;

    const int nkv = 2 * qb + 2;
    const int br = (lane & 7) + ((lane >> 4) & 1) * 8;
    const int bk = ((lane >> 3) & 1) * 8;
    const float invd2 = 1.0f / ((float)DH * (float)DH);

    auto load_tile = [&](int kj, int buf) {
        __nv_bfloat16* base = sb2 + buf * STAGE;
        const int kv0 = kj * 64;
        const __nv_bfloat16* src[4] = {kh, kl, k2h, k2l};
#pragma unroll
        for (int a = 0; a < 4; a++) {
            __nv_bfloat16* dst = base + a * ATILE;
            for (int i = tid; i < 512; i += 256) {
                const int r = i >> 3, ck = (i & 7) * 8;
                cpa16(dst + r * KST + ck, src[a] + bh_off + (size_t)(kv0 + r) * DD + ck);
            }
        }
        {
            const int r  = tid & 63;
            const int dg = (tid >> 6) * 16;
            const __nv_bfloat16* s1p = vh + bh_off + (size_t)(kv0 + r) * DD + dg;
            const __nv_bfloat16* s2p = vl + bh_off + (size_t)(kv0 + r) * DD + dg;
            unsigned short t1[16], t2[16];
            *(uint4*)t1       = *(const uint4*)s1p;
            *(uint4*)(t1 + 8) = *(const uint4*)(s1p + 8);
            *(uint4*)t2       = *(const uint4*)s2p;
            *(uint4*)(t2 + 8) = *(const uint4*)(s2p + 8);
            unsigned short* dh = (unsigned short*)(base + 4 * ATILE);
            unsigned short* dl = (unsigned short*)(base + 5 * ATILE);
#pragma unroll
            for (int j = 0; j < 16; j++) {
                dh[(dg + j) * KST + r] = t1[j];
                dl[(dg + j) * KST + r] = t2[j];
            }
        }
    };

    load_tile(0, 0);
    cpa_commit();

    for (int kj = 0; kj < nkv; kj++) {
        cpa_wait0();
        __syncthreads();
        if (kj + 1 < nkv) {
            load_tile(kj + 1, (kj + 1) & 1);
            cpa_commit();
        }

        const __nv_bfloat16* base = sb2 + (kj & 1) * STAGE;
        const int kv0 = kj * 64;
        const bool masked = (kv0 >= q0);

        uint32_t ph[8][2], pl[8][2];
#pragma unroll
        for (int g = 0; g < 4; g++) {
            float s1f[2][4], s2f[2][4];
#pragma unroll
            for (int p = 0; p < 2; p++)
#pragma unroll
                for (int e = 0; e < 4; e++) { s1f[p][e] = 0.0f; s2f[p][e] = 0.0f; }

#pragma unroll
            for (int kf = 0; kf < 4; kf++) {
                uint32_t bh_[4], bl_[4];
                const int off = (g * 16 + br) * KST + kf * 16 + bk;
                ldmat_x4(bh_, saddr(base + 0 * ATILE + off));
                ldmat_x4(bl_, saddr(base + 1 * ATILE + off));
#pragma unroll
                for (int p = 0; p < 2; p++) {
                    mma16816(s1f[p], fqh[kf], bh_[p*2], bh_[p*2+1]);
                    mma16816(s1f[p], fqh[kf], bl_[p*2], bl_[p*2+1]);
                    mma16816(s1f[p], fql[kf], bh_[p*2], bh_[p*2+1]);
                }
                ldmat_x4(bh_, saddr(base + 2 * ATILE + off));
                ldmat_x4(bl_, saddr(base + 3 * ATILE + off));
#pragma unroll
                for (int p = 0; p < 2; p++) {
                    mma16816(s2f[p], fq2h[kf], bh_[p*2], bh_[p*2+1]);
                    mma16816(s2f[p], fq2h[kf], bl_[p*2], bl_[p*2+1]);
                    mma16816(s2f[p], fq2l[kf], bh_[p*2], bh_[p*2+1]);
                }
            }
#pragma unroll
            for (int p = 0; p < 2; p++) {
                const int j = g * 2 + p;
                float pr[4];
#pragma unroll
                for (int e = 0; e < 4; e++) pr[e] = s1f[p][e] * s2f[p][e] * invd2;
                if (masked) {
                    const int qr = q0 + w * 16 + (lane >> 2);
                    const int kc = kv0 + j * 8 + (lane & 3) * 2;
                    if (kc     > qr)     pr[0] = 0.0f;
                    if (kc + 1 > qr)     pr[1] = 0.0f;
                    if (kc     > qr + 8) pr[2] = 0.0f;
                    if (kc + 1 > qr + 8) pr[3] = 0.0f;
                }
                unsigned short hh[4], ll[4];
#pragma unroll
                for (int e = 0; e < 4; e++) fsplit(pr[e], hh[e], ll[e]);
                ph[j][0] = (uint32_t)hh[1] << 16 | hh[0];
                ph[j][1] = (uint32_t)hh[3] << 16 | hh[2];
                pl[j][0] = (uint32_t)ll[1] << 16 | ll[0];
                pl[j][1] = (uint32_t)ll[3] << 16 | ll[2];
            }
        }

#pragma unroll
        for (int f = 0; f < 4; f++) {
            uint32_t ah[4] = {ph[2*f][0], ph[2*f][1], ph[2*f+1][0], ph[2*f+1][1]};
            uint32_t al[4] = {pl[2*f][0], pl[2*f][1], pl[2*f+1][0], pl[2*f+1][1]};
#pragma unroll
            for (int gd = 0; gd < 4; gd++) {
                uint32_t vh_[4], vl_[4];
                const int off = (gd * 16 + br) * KST + f * 16 + bk;
                ldmat_x4(vh_, saddr(base + 4 * ATILE + off));
                ldmat_x4(vl_, saddr(base + 5 * ATILE + off));
#pragma unroll
                for (int p = 0; p < 2; p++) {
                    mma16816(zacc[gd*2+p], ah, vh_[p*2], vh_[p*2+1]);
                    mma16816(zacc[gd*2+p], ah, vl_[p*2], vl_[p*2+1]);
                    mma16816(zacc[gd*2+p], al, vh_[p*2], vh_[p*2+1]);
                }
            }
        }
    }

    {
        const int r = q0 + w * 16 + (lane >> 2);
        const int c = (lane & 3) * 2;
#pragma unroll
        for (int nd = 0; nd < 8; nd++) {
            unsigned short h0, l0, h1, l1;
#pragma unroll
            for (int half = 0; half < 2; half++) {
                fsplit(zacc[nd][half * 2 + 0], h0, l0);
                fsplit(zacc[nd][half * 2 + 1], h1, l1);
                const size_t off = bh_off + (size_t)(r + half * 8) * DD + nd * 8 + c;
                *(uint32_t*)(zh + off) = (uint32_t)h1 << 16 | h0;
                *(uint32_t*)(zl + off) = (uint32_t)l1 << 16 | l0;
            }
        }
    }
}

// ---------------------------------------------------------------------------
extern "C" void kernel_launch(void* const* d_in, const int* in_sizes, int n_in,
                              void* d_out, int out_size) {
    const float* x     = (const float*)d_in[0];
    const float* Wq    = (const float*)d_in[1];
    const float* Wk    = (const float*)d_in[2];
    const float* Wq2   = (const float*)d_in[3];
    const float* Wk2   = (const float*)d_in[4];
    const float* Wv    = (const float*)d_in[5];
    const float* Wproj = (const float*)d_in[6];
    float* out = (float*)d_out;

    float* p5;
    cudaGetSymbolAddress((void**)&p5, g_p5);

    __nv_bfloat16 *xh, *xl, *zh, *zl, *w6h, *w6l;
    cudaGetSymbolAddress((void**)&xh,  g_xh);  cudaGetSymbolAddress((void**)&xl,  g_xl);
    cudaGetSymbolAddress((void**)&zh,  g_zh);  cudaGetSymbolAddress((void**)&zl,  g_zl);
    cudaGetSymbolAddress((void**)&w6h, g_w6h); cudaGetSymbolAddress((void**)&w6l, g_w6l);

    __nv_bfloat16 *qh, *ql, *q2h, *q2l, *kh, *kl, *k2h, *k2l, *vh, *vl;
    cudaGetSymbolAddress((void**)&qh,  g_qh);  cudaGetSymbolAddress((void**)&ql,  g_ql);
    cudaGetSymbolAddress((void**)&q2h, g_q2h); cudaGetSymbolAddress((void**)&q2l, g_q2l);
    cudaGetSymbolAddress((void**)&kh,  g_kh);  cudaGetSymbolAddress((void**)&kl,  g_kl);
    cudaGetSymbolAddress((void**)&k2h, g_k2h); cudaGetSymbolAddress((void**)&k2l, g_k2l);
    cudaGetSymbolAddress((void**)&vh,  g_vh);  cudaGetSymbolAddress((void**)&vl,  g_vl);

    cudaFuncSetAttribute(gemm_bf16,
                         cudaFuncAttributeMaxDynamicSharedMemorySize, GEMM_SMEM);

    // 1) split inputs
    split_f32<<<MM * DD / 1024, 256>>>(x, xh, xl);
    split_w6<<<dim3(DD * DD / 1024, 6), 256>>>(Wq, Wk, Wq2, Wk2, Wv, Wproj, w6h, w6l);

    // 2) five fused projections (512 threads, 16 warps)
    gemm_bf16<<<dim3(DD / 128, MM / 128, 5), 512, GEMM_SMEM>>>(xh, xl, w6h, w6l, p5);

    // 3) rope + split
    rope_split<<<(BB * TT * HH * 32) / 256, 256>>>(p5, qh, ql, kh, kl,
                                                   q2h, q2l, k2h, k2l, vh, vl);

    // 4) attention (writes zh/zl directly)
    const int attn_smem = 2 * STAGE * (int)sizeof(__nv_bfloat16);
    cudaFuncSetAttribute(attn_mma,
                         cudaFuncAttributeMaxDynamicSharedMemorySize, attn_smem);
    attn_mma<<<dim3(TT / 128, BB * HH), 256, attn_smem>>>(
        qh, ql, q2h, q2l, kh, kl, k2h, k2l, vh, vl, zh, zl);

    // 5) output projection
    gemm_bf16<<<dim3(DD / 128, MM / 128, 1), 512, GEMM_SMEM>>>(
        zh, zl, w6h + (size_t)5 * DD * DD, w6l + (size_t)5 * DD * DD, out);
}

// round 9
// speedup vs baseline: 1.0627x; 1.0278x over previous
#include <cuda_runtime.h>
#include <cuda_bf16.h>
#include <math.h>
#include <stdint.h>

#define BB 2
#define TT 2048
#define DD 1024
#define HH 16
#define DH 64
#define MM (BB*TT)

/* ---- gemm geometry: CTA 128x128, 8 warps (64x32), k-chunk 64, 3-stage ---- */
#define GST 72
#define GTILE (128*GST)
#define GSTAGE (4*GTILE)
#define NSTG 3
#define NCH  16
#define GEMM_SMEM (NSTG*GSTAGE*2)   /* 221184 B */

#define KST 72
#define ATILE (64*KST)
#define STAGE (6*ATILE)

// ---------------- scratch (device globals) ----------------------------------
__device__ float g_p5[5*MM*DD];
__device__ __nv_bfloat16 g_xh [MM*DD], g_xl [MM*DD];
__device__ __nv_bfloat16 g_zh [MM*DD], g_zl [MM*DD];
__device__ __nv_bfloat16 g_w6h[6*DD*DD], g_w6l[6*DD*DD];
__device__ __nv_bfloat16 g_qh [MM*DD], g_ql [MM*DD];
__device__ __nv_bfloat16 g_q2h[MM*DD], g_q2l[MM*DD];
__device__ __nv_bfloat16 g_kh [MM*DD], g_kl [MM*DD];
__device__ __nv_bfloat16 g_k2h[MM*DD], g_k2l[MM*DD];
__device__ __nv_bfloat16 g_vh [MM*DD], g_vl [MM*DD];

// ---------------------------------------------------------------------------
__device__ __forceinline__ uint32_t saddr(const void* p) {
    return (uint32_t)__cvta_generic_to_shared(p);
}
__device__ __forceinline__ void ldmat_x4(uint32_t (&r)[4], uint32_t a) {
    asm volatile("ldmatrix.sync.aligned.m8n8.x4.shared.b16 {%0,%1,%2,%3}, [%4];"
                 : "=r"(r[0]), "=r"(r[1]), "=r"(r[2]), "=r"(r[3]) : "r"(a));
}
__device__ __forceinline__ void mma16816(float (&d)[4], const uint32_t (&a)[4],
                                         uint32_t b0, uint32_t b1) {
    asm volatile(
        "mma.sync.aligned.m16n8k16.row.col.f32.bf16.bf16.f32 "
        "{%0,%1,%2,%3}, {%4,%5,%6,%7}, {%8,%9}, {%0,%1,%2,%3};"
        : "+f"(d[0]), "+f"(d[1]), "+f"(d[2]), "+f"(d[3])
        : "r"(a[0]), "r"(a[1]), "r"(a[2]), "r"(a[3]), "r"(b0), "r"(b1));
}
__device__ __forceinline__ void cpa16(void* dst, const void* src) {
    asm volatile("cp.async.cg.shared.global [%0], [%1], 16;"
                 :: "r"(saddr(dst)), "l"(src));
}
__device__ __forceinline__ void cpa_commit() { asm volatile("cp.async.commit_group;"); }
__device__ __forceinline__ void cpa_wait0()  { asm volatile("cp.async.wait_group 0;"); }
__device__ __forceinline__ void cpa_wait1()  { asm volatile("cp.async.wait_group 1;"); }

__device__ __forceinline__ void fsplit(float x, unsigned short& h, unsigned short& l) {
    __nv_bfloat16 hb = __float2bfloat16_rn(x);
    __nv_bfloat16 lb = __float2bfloat16_rn(x - __bfloat162float(hb));
    h = __bfloat16_as_ushort(hb);
    l = __bfloat16_as_ushort(lb);
}

// ---------------------------------------------------------------------------
// splits
// ---------------------------------------------------------------------------
__global__ void split_f32(const float* __restrict__ in,
                          __nv_bfloat16* __restrict__ hi,
                          __nv_bfloat16* __restrict__ lo) {
    const size_t i = ((size_t)blockIdx.x * 256 + threadIdx.x) * 4;
    float4 v = *(const float4*)(in + i);
    float f[4] = {v.x, v.y, v.z, v.w};
    unsigned short h[4], l[4];
#pragma unroll
    for (int e = 0; e < 4; e++) fsplit(f[e], h[e], l[e]);
    *(uint2*)(hi + i) = make_uint2((uint32_t)h[1] << 16 | h[0],
                                   (uint32_t)h[3] << 16 | h[2]);
    *(uint2*)(lo + i) = make_uint2((uint32_t)l[1] << 16 | l[0],
                                   (uint32_t)l[3] << 16 | l[2]);
}

__global__ void split_w6(const float* __restrict__ w0, const float* __restrict__ w1,
                         const float* __restrict__ w2, const float* __restrict__ w3,
                         const float* __restrict__ w4, const float* __restrict__ w5,
                         __nv_bfloat16* __restrict__ hi, __nv_bfloat16* __restrict__ lo) {
    const float* src[6] = {w0, w1, w2, w3, w4, w5};
    const float* in = src[blockIdx.y];
    const size_t off = (size_t)blockIdx.y * DD * DD;
    const size_t i = ((size_t)blockIdx.x * 256 + threadIdx.x) * 4;
    float4 v = *(const float4*)(in + i);
    float f[4] = {v.x, v.y, v.z, v.w};
    unsigned short h[4], l[4];
#pragma unroll
    for (int e = 0; e < 4; e++) fsplit(f[e], h[e], l[e]);
    *(uint2*)(hi + off + i) = make_uint2((uint32_t)h[1] << 16 | h[0],
                                         (uint32_t)h[3] << 16 | h[2]);
    *(uint2*)(lo + off + i) = make_uint2((uint32_t)l[1] << 16 | l[0],
                                         (uint32_t)l[3] << 16 | l[2]);
}

// ---------------------------------------------------------------------------
// C[M,N] = A[M,K] @ W[N,K]^T, bf16 hi/lo 3-term mma.sync, TERM-MAJOR order.
// CTA 128x128, 8 warps (64x32 each), k-chunk 64, 3-stage cp.async ring.
// ---------------------------------------------------------------------------
__global__ void __launch_bounds__(256, 1) gemm_bf16(
        const __nv_bfloat16* __restrict__ Ah, const __nv_bfloat16* __restrict__ Al,
        const __nv_bfloat16* __restrict__ Wh, const __nv_bfloat16* __restrict__ Wl,
        float* __restrict__ C) {
    extern __shared__ __nv_bfloat16 sg[];
    const int zi = blockIdx.z;
    Wh += (size_t)zi * DD * DD;
    Wl += (size_t)zi * DD * DD;
    C  += (size_t)zi * MM * DD;

    const int tid  = threadIdx.x;
    const int wid  = tid >> 5;
    const int lane = tid & 31;
    const int m0 = blockIdx.y * 128;
    const int n0 = blockIdx.x * 128;
    const int wm = wid & 1;
    const int wn = wid >> 1;

    auto load_chunk = [&](int c) {
        __nv_bfloat16* base = sg + (c % NSTG) * GSTAGE;
        const int k0 = c * 64;
#pragma unroll 4
        for (int i = tid; i < 1024; i += 256) {
            const int r  = i >> 3;
            const int ck = (i & 7) * 8;
            const int so = r * GST + ck;
            cpa16(base + 0 * GTILE + so, Ah + (size_t)(m0 + r) * DD + k0 + ck);
            cpa16(base + 1 * GTILE + so, Al + (size_t)(m0 + r) * DD + k0 + ck);
            cpa16(base + 2 * GTILE + so, Wh + (size_t)(n0 + r) * DD + k0 + ck);
            cpa16(base + 3 * GTILE + so, Wl + (size_t)(n0 + r) * DD + k0 + ck);
        }
        cpa_commit();
    };

    float acc[4][4][4];
#pragma unroll
    for (int i = 0; i < 4; i++)
#pragma unroll
        for (int j = 0; j < 4; j++)
#pragma unroll
            for (int c = 0; c < 4; c++) acc[i][j][c] = 0.0f;

    load_chunk(0);
    load_chunk(1);

    for (int ch = 0; ch < NCH; ch++) {
        if (ch + 1 < NCH) cpa_wait1();
        else              cpa_wait0();
        __syncthreads();
        if (ch + 2 < NCH) load_chunk(ch + 2);

        const __nv_bfloat16* cur = sg + (ch % NSTG) * GSTAGE;
        const __nv_bfloat16* Ahi = cur;
        const __nv_bfloat16* Alo = cur + GTILE;
        const __nv_bfloat16* Bhi = cur + 2 * GTILE;
        const __nv_bfloat16* Blo = cur + 3 * GTILE;

#pragma unroll
        for (int kk = 0; kk < 4; kk++) {
            uint32_t ahi[4][4], alo[4][4], bhi[2][4], blo[2][4];
            const int ar = wm * 64 + (lane & 15);
            const int ak = kk * 16 + (lane >> 4) * 8;
#pragma unroll
            for (int mi = 0; mi < 4; mi++) {
                ldmat_x4(ahi[mi], saddr(Ahi + (ar + mi * 16) * GST + ak));
                ldmat_x4(alo[mi], saddr(Alo + (ar + mi * 16) * GST + ak));
            }
            const int br = wn * 32 + ((lane >> 4) & 1) * 8 + (lane & 7);
            const int bk = kk * 16 + ((lane >> 3) & 1) * 8;
#pragma unroll
            for (int p = 0; p < 2; p++) {
                ldmat_x4(bhi[p], saddr(Bhi + (br + p * 16) * GST + bk));
                ldmat_x4(blo[p], saddr(Blo + (br + p * 16) * GST + bk));
            }
            // term-major: same-acc reuse distance = 16 independent mmas
#pragma unroll
            for (int mi = 0; mi < 4; mi++)
#pragma unroll
                for (int ni = 0; ni < 4; ni++) {
                    const uint32_t* bh = &bhi[ni >> 1][(ni & 1) * 2];
                    mma16816(acc[mi][ni], ahi[mi], bh[0], bh[1]);
                }
#pragma unroll
            for (int mi = 0; mi < 4; mi++)
#pragma unroll
                for (int ni = 0; ni < 4; ni++) {
                    const uint32_t* bl = &blo[ni >> 1][(ni & 1) * 2];
                    mma16816(acc[mi][ni], ahi[mi], bl[0], bl[1]);
                }
#pragma unroll
            for (int mi = 0; mi < 4; mi++)
#pragma unroll
                for (int ni = 0; ni < 4; ni++) {
                    const uint32_t* bh = &bhi[ni >> 1][(ni & 1) * 2];
                    mma16816(acc[mi][ni], alo[mi], bh[0], bh[1]);
                }
        }
    }

#pragma unroll
    for (int mi = 0; mi < 4; mi++)
#pragma unroll
        for (int ni = 0; ni < 4; ni++) {
            const int r0 = m0 + wm * 64 + mi * 16 + (lane >> 2);
            const int c0 = n0 + wn * 32 + ni * 8 + (lane & 3) * 2;
            *(float2*)(C + (size_t)r0 * 1024 + c0) =
                make_float2(acc[mi][ni][0], acc[mi][ni][1]);
            *(float2*)(C + (size_t)(r0 + 8) * 1024 + c0) =
                make_float2(acc[mi][ni][2], acc[mi][ni][3]);
        }
}

// ---------------------------------------------------------------------------
// RoPE + split to bf16 hi/lo
// ---------------------------------------------------------------------------
__global__ void rope_split(const float* __restrict__ p5,
                           __nv_bfloat16* __restrict__ qh,  __nv_bfloat16* __restrict__ ql,
                           __nv_bfloat16* __restrict__ kh,  __nv_bfloat16* __restrict__ kl,
                           __nv_bfloat16* __restrict__ q2h, __nv_bfloat16* __restrict__ q2l,
                           __nv_bfloat16* __restrict__ k2h, __nv_bfloat16* __restrict__ k2l,
                           __nv_bfloat16* __restrict__ vh,  __nv_bfloat16* __restrict__ vl) {
    const int idx = blockIdx.x * blockDim.x + threadIdx.x;
    const int i = idx & 31;
    const int h = (idx >> 5) & (HH - 1);
    const int t = (idx >> 9) & (TT - 1);
    const int b = idx >> 20;

    const float inv_freq = powf(10000.0f, -(float)i * (1.0f / 32.0f));
    float c, s;
    sincosf((float)t * inv_freq, &s, &c);

    const size_t base = ((size_t)(b * TT + t)) * DD + h * DH + i;

    __nv_bfloat16* oh[4] = {qh, kh, q2h, k2h};
    __nv_bfloat16* ol[4] = {ql, kl, q2l, k2l};
#pragma unroll
    for (int a = 0; a < 4; a++) {
        const float* in = p5 + (size_t)a * MM * DD;
        float x1 = in[base];
        float x2 = in[base + 32];
        float y1 = fmaf(x1, c, x2 * s);
        float y2 = fmaf(-x1, s, x2 * c);
        unsigned short hh, lll;
        fsplit(y1, hh, lll);
        oh[a][base]      = __ushort_as_bfloat16(hh);
        ol[a][base]      = __ushort_as_bfloat16(lll);
        fsplit(y2, hh, lll);
        oh[a][base + 32] = __ushort_as_bfloat16(hh);
        ol[a][base + 32] = __ushort_as_bfloat16(lll);
    }
    {
        const float* vv = p5 + (size_t)4 * MM * DD;
        unsigned short hh, lll;
        fsplit(vv[base], hh, lll);
        vh[base]      = __ushort_as_bfloat16(hh);
        vl[base]      = __ushort_as_bfloat16(lll);
        fsplit(vv[base + 32], hh, lll);
        vh[base + 32] = __ushort_as_bfloat16(hh);
        vl[base + 32] = __ushort_as_bfloat16(lll);
    }
}

// ---------------------------------------------------------------------------
// Tensor-core causal bilinear attention; term-major mma ordering.
// ---------------------------------------------------------------------------
__global__ void __launch_bounds__(256, 1) attn_mma(
        const __nv_bfloat16* __restrict__ qh,  const __nv_bfloat16* __restrict__ ql,
        const __nv_bfloat16* __restrict__ q2h, const __nv_bfloat16* __restrict__ q2l,
        const __nv_bfloat16* __restrict__ kh,  const __nv_bfloat16* __restrict__ kl,
        const __nv_bfloat16* __restrict__ k2h, const __nv_bfloat16* __restrict__ k2l,
        const __nv_bfloat16* __restrict__ vh,  const __nv_bfloat16* __restrict__ vl,
        __nv_bfloat16* __restrict__ zh, __nv_bfloat16* __restrict__ zl) {
    extern __shared__ __nv_bfloat16 sb2[];
    const int tid  = threadIdx.x;
    const int lane = tid & 31;
    const int w    = tid >> 5;
    const int qb = (int)gridDim.x - 1 - (int)blockIdx.x;
    const int q0 = qb * 128;
    const int b  = blockIdx.y >> 4;
    const int h  = blockIdx.y & 15;
    const size_t bh_off = (size_t)b * TT * DD + h * DH;

    {
        const __nv_bfloat16* src[4] = {qh, ql, q2h, q2l};
#pragma unroll
        for (int a = 0; a < 4; a++) {
            __nv_bfloat16* dst = sb2 + a * 128 * KST;
            for (int i = tid; i < 1024; i += 256) {
                const int r = i >> 3, ck = (i & 7) * 8;
                cpa16(dst + r * KST + ck, src[a] + bh_off + (size_t)(q0 + r) * DD + ck);
            }
        }
        cpa_commit();
        cpa_wait0();
        __syncthreads();
    }

    uint32_t fqh[4][4], fql[4][4], fq2h[4][4], fq2l[4][4];
    {
        const int ar = w * 16 + (lane & 15);
        const int ak = (lane >> 4) * 8;
#pragma unroll
        for (int kf = 0; kf < 4; kf++) {
            ldmat_x4(fqh [kf], saddr(sb2 + 0 * 128 * KST + ar * KST + kf * 16 + ak));
            ldmat_x4(fql [kf], saddr(sb2 + 1 * 128 * KST + ar * KST + kf * 16 + ak));
            ldmat_x4(fq2h[kf], saddr(sb2 + 2 * 128 * KST + ar * KST + kf * 16 + ak));
            ldmat_x4(fq2l[kf], saddr(sb2 + 3 * 128 * KST + ar * KST + kf * 16 + ak));
        }
    }
    __syncthreads();

    float zacc[8][4];
#pragma unroll
    for (int i = 0; i < 8; i++)
#pragma unroll
        for (int j = 0; j < 4; j++) zacc[i][j] = 0.0f;

    const int nkv = 2 * qb + 2;
    const int br = (lane & 7) + ((lane >> 4) & 1) * 8;
    const int bk = ((lane >> 3) & 1) * 8;
    const float invd2 = 1.0f / ((float)DH * (float)DH);

    auto load_tile = [&](int kj, int buf) {
        __nv_bfloat16* base = sb2 + buf * STAGE;
        const int kv0 = kj * 64;
        const __nv_bfloat16* src[4] = {kh, kl, k2h, k2l};
#pragma unroll
        for (int a = 0; a < 4; a++) {
            __nv_bfloat16* dst = base + a * ATILE;
            for (int i = tid; i < 512; i += 256) {
                const int r = i >> 3, ck = (i & 7) * 8;
                cpa16(dst + r * KST + ck, src[a] + bh_off + (size_t)(kv0 + r) * DD + ck);
            }
        }
        {
            const int r  = tid & 63;
            const int dg = (tid >> 6) * 16;
            const __nv_bfloat16* s1p = vh + bh_off + (size_t)(kv0 + r) * DD + dg;
            const __nv_bfloat16* s2p = vl + bh_off + (size_t)(kv0 + r) * DD + dg;
            unsigned short t1[16], t2[16];
            *(uint4*)t1       = *(const uint4*)s1p;
            *(uint4*)(t1 + 8) = *(const uint4*)(s1p + 8);
            *(uint4*)t2       = *(const uint4*)s2p;
            *(uint4*)(t2 + 8) = *(const uint4*)(s2p + 8);
            unsigned short* dh = (unsigned short*)(base + 4 * ATILE);
            unsigned short* dl = (unsigned short*)(base + 5 * ATILE);
#pragma unroll
            for (int j = 0; j < 16; j++) {
                dh[(dg + j) * KST + r] = t1[j];
                dl[(dg + j) * KST + r] = t2[j];
            }
        }
    };

    load_tile(0, 0);
    cpa_commit();

    for (int kj = 0; kj < nkv; kj++) {
        cpa_wait0();
        __syncthreads();
        if (kj + 1 < nkv) {
            load_tile(kj + 1, (kj + 1) & 1);
            cpa_commit();
        }

        const __nv_bfloat16* base = sb2 + (kj & 1) * STAGE;
        const int kv0 = kj * 64;
        const bool masked = (kv0 >= q0);

        uint32_t ph[8][2], pl[8][2];
#pragma unroll
        for (int g = 0; g < 4; g++) {
            float s1f[2][4], s2f[2][4];
#pragma unroll
            for (int p = 0; p < 2; p++)
#pragma unroll
                for (int e = 0; e < 4; e++) { s1f[p][e] = 0.0f; s2f[p][e] = 0.0f; }

#pragma unroll
            for (int kf = 0; kf < 4; kf++) {
                uint32_t kh_[4], kl_[4], k2h_[4], k2l_[4];
                const int off = (g * 16 + br) * KST + kf * 16 + bk;
                ldmat_x4(kh_,  saddr(base + 0 * ATILE + off));
                ldmat_x4(kl_,  saddr(base + 1 * ATILE + off));
                ldmat_x4(k2h_, saddr(base + 2 * ATILE + off));
                ldmat_x4(k2l_, saddr(base + 3 * ATILE + off));
                // term-major, s1/s2 interleaved: same-acc distance 4
#pragma unroll
                for (int p = 0; p < 2; p++) {
                    mma16816(s1f[p], fqh[kf],  kh_[p*2],  kh_[p*2+1]);
                    mma16816(s2f[p], fq2h[kf], k2h_[p*2], k2h_[p*2+1]);
                }
#pragma unroll
                for (int p = 0; p < 2; p++) {
                    mma16816(s1f[p], fqh[kf],  kl_[p*2],  kl_[p*2+1]);
                    mma16816(s2f[p], fq2h[kf], k2l_[p*2], k2l_[p*2+1]);
                }
#pragma unroll
                for (int p = 0; p < 2; p++) {
                    mma16816(s1f[p], fql[kf],  kh_[p*2],  kh_[p*2+1]);
                    mma16816(s2f[p], fq2l[kf], k2h_[p*2], k2h_[p*2+1]);
                }
            }
#pragma unroll
            for (int p = 0; p < 2; p++) {
                const int j = g * 2 + p;
                float pr[4];
#pragma unroll
                for (int e = 0; e < 4; e++) pr[e] = s1f[p][e] * s2f[p][e] * invd2;
                if (masked) {
                    const int qr = q0 + w * 16 + (lane >> 2);
                    const int kc = kv0 + j * 8 + (lane & 3) * 2;
                    if (kc     > qr)     pr[0] = 0.0f;
                    if (kc + 1 > qr)     pr[1] = 0.0f;
                    if (kc     > qr + 8) pr[2] = 0.0f;
                    if (kc + 1 > qr + 8) pr[3] = 0.0f;
                }
                unsigned short hh[4], ll[4];
#pragma unroll
                for (int e = 0; e < 4; e++) fsplit(pr[e], hh[e], ll[e]);
                ph[j][0] = (uint32_t)hh[1] << 16 | hh[0];
                ph[j][1] = (uint32_t)hh[3] << 16 | hh[2];
                pl[j][0] = (uint32_t)ll[1] << 16 | ll[0];
                pl[j][1] = (uint32_t)ll[3] << 16 | ll[2];
            }
        }

        // PV: hoist all gd ldmatrix loads, then term-major (distance 8)
#pragma unroll
        for (int f = 0; f < 4; f++) {
            uint32_t ah[4] = {ph[2*f][0], ph[2*f][1], ph[2*f+1][0], ph[2*f+1][1]};
            uint32_t al[4] = {pl[2*f][0], pl[2*f][1], pl[2*f+1][0], pl[2*f+1][1]};
            uint32_t vh_[4][4], vl_[4][4];
#pragma unroll
            for (int gd = 0; gd < 4; gd++) {
                const int off = (gd * 16 + br) * KST + f * 16 + bk;
                ldmat_x4(vh_[gd], saddr(base + 4 * ATILE + off));
                ldmat_x4(vl_[gd], saddr(base + 5 * ATILE + off));
            }
#pragma unroll
            for (int gd = 0; gd < 4; gd++)
#pragma unroll
                for (int p = 0; p < 2; p++)
                    mma16816(zacc[gd*2+p], ah, vh_[gd][p*2], vh_[gd][p*2+1]);
#pragma unroll
            for (int gd = 0; gd < 4; gd++)
#pragma unroll
                for (int p = 0; p < 2; p++)
                    mma16816(zacc[gd*2+p], ah, vl_[gd][p*2], vl_[gd][p*2+1]);
#pragma unroll
            for (int gd = 0; gd < 4; gd++)
#pragma unroll
                for (int p = 0; p < 2; p++)
                    mma16816(zacc[gd*2+p], al, vh_[gd][p*2], vh_[gd][p*2+1]);
        }
    }

    {
        const int r = q0 + w * 16 + (lane >> 2);
        const int c = (lane & 3) * 2;
#pragma unroll
        for (int nd = 0; nd < 8; nd++) {
            unsigned short h0, l0, h1, l1;
#pragma unroll
            for (int half = 0; half < 2; half++) {
                fsplit(zacc[nd][half * 2 + 0], h0, l0);
                fsplit(zacc[nd][half * 2 + 1], h1, l1);
                const size_t off = bh_off + (size_t)(r + half * 8) * DD + nd * 8 + c;
                *(uint32_t*)(zh + off) = (uint32_t)h1 << 16 | h0;
                *(uint32_t*)(zl + off) = (uint32_t)l1 << 16 | l0;
            }
        }
    }
}

// ---------------------------------------------------------------------------
extern "C" void kernel_launch(void* const* d_in, const int* in_sizes, int n_in,
                              void* d_out, int out_size) {
    const float* x     = (const float*)d_in[0];
    const float* Wq    = (const float*)d_in[1];
    const float* Wk    = (const float*)d_in[2];
    const float* Wq2   = (const float*)d_in[3];
    const float* Wk2   = (const float*)d_in[4];
    const float* Wv    = (const float*)d_in[5];
    const float* Wproj = (const float*)d_in[6];
    float* out = (float*)d_out;

    float* p5;
    cudaGetSymbolAddress((void**)&p5, g_p5);

    __nv_bfloat16 *xh, *xl, *zh, *zl, *w6h, *w6l;
    cudaGetSymbolAddress((void**)&xh,  g_xh);  cudaGetSymbolAddress((void**)&xl,  g_xl);
    cudaGetSymbolAddress((void**)&zh,  g_zh);  cudaGetSymbolAddress((void**)&zl,  g_zl);
    cudaGetSymbolAddress((void**)&w6h, g_w6h); cudaGetSymbolAddress((void**)&w6l, g_w6l);

    __nv_bfloat16 *qh, *ql, *q2h, *q2l, *kh, *kl, *k2h, *k2l, *vh, *vl;
    cudaGetSymbolAddress((void**)&qh,  g_qh);  cudaGetSymbolAddress((void**)&ql,  g_ql);
    cudaGetSymbolAddress((void**)&q2h, g_q2h); cudaGetSymbolAddress((void**)&q2l, g_q2l);
    cudaGetSymbolAddress((void**)&kh,  g_kh);  cudaGetSymbolAddress((void**)&kl,  g_kl);
    cudaGetSymbolAddress((void**)&k2h, g_k2h); cudaGetSymbolAddress((void**)&k2l, g_k2l);
    cudaGetSymbolAddress((void**)&vh,  g_vh);  cudaGetSymbolAddress((void**)&vl,  g_vl);

    cudaFuncSetAttribute(gemm_bf16,
                         cudaFuncAttributeMaxDynamicSharedMemorySize, GEMM_SMEM);

    // 1) split inputs
    split_f32<<<MM * DD / 1024, 256>>>(x, xh, xl);
    split_w6<<<dim3(DD * DD / 1024, 6), 256>>>(Wq, Wk, Wq2, Wk2, Wv, Wproj, w6h, w6l);

    // 2) five fused projections
    gemm_bf16<<<dim3(DD / 128, MM / 128, 5), 256, GEMM_SMEM>>>(xh, xl, w6h, w6l, p5);

    // 3) rope + split
    rope_split<<<(BB * TT * HH * 32) / 256, 256>>>(p5, qh, ql, kh, kl,
                                                   q2h, q2l, k2h, k2l, vh, vl);

    // 4) attention (writes zh/zl directly)
    const int attn_smem = 2 * STAGE * (int)sizeof(__nv_bfloat16);
    cudaFuncSetAttribute(attn_mma,
                         cudaFuncAttributeMaxDynamicSharedMemorySize, attn_smem);
    attn_mma<<<dim3(TT / 128, BB * HH), 256, attn_smem>>>(
        qh, ql, q2h, q2l, kh, kl, k2h, k2l, vh, vl, zh, zl);

    // 5) output projection
    gemm_bf16<<<dim3(DD / 128, MM / 128, 1), 256, GEMM_SMEM>>>(
        zh, zl, w6h + (size_t)5 * DD * DD, w6l + (size_t)5 * DD * DD, out);
}

// round 10
// speedup vs baseline: 1.1724x; 1.1031x over previous
#include <cuda_runtime.h>
#include <cuda_bf16.h>
#include <math.h>
#include <stdint.h>

#define BB 2
#define TT 2048
#define DD 1024
#define HH 16
#define DH 64
#define MM (BB*TT)

/* ---- gemm geometry: CTA 128x128, 8 warps (64x32), k-chunk 64, 3-stage ---- */
#define GST 72
#define GTILE (128*GST)
#define GSTAGE (4*GTILE)
#define NSTG 3
#define NCH  16
#define GEMM_SMEM (NSTG*GSTAGE*2)   /* 221184 B */

#define KST 72
#define ATILE (64*KST)
#define STAGE (6*ATILE)

// ---------------- scratch (device globals) ----------------------------------
__device__ float g_p5[5*MM*DD];
__device__ __nv_bfloat16 g_xh [MM*DD], g_xl [MM*DD];
__device__ __nv_bfloat16 g_zh [MM*DD], g_zl [MM*DD];
__device__ __nv_bfloat16 g_w6h[6*DD*DD], g_w6l[6*DD*DD];
__device__ __nv_bfloat16 g_qh [MM*DD], g_ql [MM*DD];
__device__ __nv_bfloat16 g_q2h[MM*DD], g_q2l[MM*DD];
__device__ __nv_bfloat16 g_kh [MM*DD], g_kl [MM*DD];
__device__ __nv_bfloat16 g_k2h[MM*DD], g_k2l[MM*DD];
__device__ __nv_bfloat16 g_vh [MM*DD], g_vl [MM*DD];

// ---------------------------------------------------------------------------
__device__ __forceinline__ uint32_t saddr(const void* p) {
    return (uint32_t)__cvta_generic_to_shared(p);
}
__device__ __forceinline__ void ldmat_x4(uint32_t (&r)[4], uint32_t a) {
    asm volatile("ldmatrix.sync.aligned.m8n8.x4.shared.b16 {%0,%1,%2,%3}, [%4];"
                 : "=r"(r[0]), "=r"(r[1]), "=r"(r[2]), "=r"(r[3]) : "r"(a));
}
__device__ __forceinline__ void ldmat_x4_trans(uint32_t (&r)[4], uint32_t a) {
    asm volatile("ldmatrix.sync.aligned.m8n8.x4.trans.shared.b16 {%0,%1,%2,%3}, [%4];"
                 : "=r"(r[0]), "=r"(r[1]), "=r"(r[2]), "=r"(r[3]) : "r"(a));
}
__device__ __forceinline__ void mma16816(float (&d)[4], const uint32_t (&a)[4],
                                         uint32_t b0, uint32_t b1) {
    asm volatile(
        "mma.sync.aligned.m16n8k16.row.col.f32.bf16.bf16.f32 "
        "{%0,%1,%2,%3}, {%4,%5,%6,%7}, {%8,%9}, {%0,%1,%2,%3};"
        : "+f"(d[0]), "+f"(d[1]), "+f"(d[2]), "+f"(d[3])
        : "r"(a[0]), "r"(a[1]), "r"(a[2]), "r"(a[3]), "r"(b0), "r"(b1));
}
__device__ __forceinline__ void cpa16(void* dst, const void* src) {
    asm volatile("cp.async.cg.shared.global [%0], [%1], 16;"
                 :: "r"(saddr(dst)), "l"(src));
}
__device__ __forceinline__ void cpa_commit() { asm volatile("cp.async.commit_group;"); }
__device__ __forceinline__ void cpa_wait0()  { asm volatile("cp.async.wait_group 0;"); }
__device__ __forceinline__ void cpa_wait1()  { asm volatile("cp.async.wait_group 1;"); }

__device__ __forceinline__ void fsplit(float x, unsigned short& h, unsigned short& l) {
    __nv_bfloat16 hb = __float2bfloat16_rn(x);
    __nv_bfloat16 lb = __float2bfloat16_rn(x - __bfloat162float(hb));
    h = __bfloat16_as_ushort(hb);
    l = __bfloat16_as_ushort(lb);
}

// ---------------------------------------------------------------------------
// splits
// ---------------------------------------------------------------------------
__global__ void split_f32(const float* __restrict__ in,
                          __nv_bfloat16* __restrict__ hi,
                          __nv_bfloat16* __restrict__ lo) {
    const size_t i = ((size_t)blockIdx.x * 256 + threadIdx.x) * 4;
    float4 v = *(const float4*)(in + i);
    float f[4] = {v.x, v.y, v.z, v.w};
    unsigned short h[4], l[4];
#pragma unroll
    for (int e = 0; e < 4; e++) fsplit(f[e], h[e], l[e]);
    *(uint2*)(hi + i) = make_uint2((uint32_t)h[1] << 16 | h[0],
                                   (uint32_t)h[3] << 16 | h[2]);
    *(uint2*)(lo + i) = make_uint2((uint32_t)l[1] << 16 | l[0],
                                   (uint32_t)l[3] << 16 | l[2]);
}

__global__ void split_w6(const float* __restrict__ w0, const float* __restrict__ w1,
                         const float* __restrict__ w2, const float* __restrict__ w3,
                         const float* __restrict__ w4, const float* __restrict__ w5,
                         __nv_bfloat16* __restrict__ hi, __nv_bfloat16* __restrict__ lo) {
    const float* src[6] = {w0, w1, w2, w3, w4, w5};
    const float* in = src[blockIdx.y];
    const size_t off = (size_t)blockIdx.y * DD * DD;
    const size_t i = ((size_t)blockIdx.x * 256 + threadIdx.x) * 4;
    float4 v = *(const float4*)(in + i);
    float f[4] = {v.x, v.y, v.z, v.w};
    unsigned short h[4], l[4];
#pragma unroll
    for (int e = 0; e < 4; e++) fsplit(f[e], h[e], l[e]);
    *(uint2*)(hi + off + i) = make_uint2((uint32_t)h[1] << 16 | h[0],
                                         (uint32_t)h[3] << 16 | h[2]);
    *(uint2*)(lo + off + i) = make_uint2((uint32_t)l[1] << 16 | l[0],
                                         (uint32_t)l[3] << 16 | l[2]);
}

// ---------------------------------------------------------------------------
// C[M,N] = A[M,K] @ W[N,K]^T, bf16 hi/lo 3-term mma.sync (round-6 geometry).
// ---------------------------------------------------------------------------
__global__ void __launch_bounds__(256, 1) gemm_bf16(
        const __nv_bfloat16* __restrict__ Ah, const __nv_bfloat16* __restrict__ Al,
        const __nv_bfloat16* __restrict__ Wh, const __nv_bfloat16* __restrict__ Wl,
        float* __restrict__ C) {
    extern __shared__ __nv_bfloat16 sg[];
    const int zi = blockIdx.z;
    Wh += (size_t)zi * DD * DD;
    Wl += (size_t)zi * DD * DD;
    C  += (size_t)zi * MM * DD;

    const int tid  = threadIdx.x;
    const int wid  = tid >> 5;
    const int lane = tid & 31;
    const int m0 = blockIdx.y * 128;
    const int n0 = blockIdx.x * 128;
    const int wm = wid & 1;
    const int wn = wid >> 1;

    auto load_chunk = [&](int c) {
        __nv_bfloat16* base = sg + (c % NSTG) * GSTAGE;
        const int k0 = c * 64;
#pragma unroll 4
        for (int i = tid; i < 1024; i += 256) {
            const int r  = i >> 3;
            const int ck = (i & 7) * 8;
            const int so = r * GST + ck;
            cpa16(base + 0 * GTILE + so, Ah + (size_t)(m0 + r) * DD + k0 + ck);
            cpa16(base + 1 * GTILE + so, Al + (size_t)(m0 + r) * DD + k0 + ck);
            cpa16(base + 2 * GTILE + so, Wh + (size_t)(n0 + r) * DD + k0 + ck);
            cpa16(base + 3 * GTILE + so, Wl + (size_t)(n0 + r) * DD + k0 + ck);
        }
        cpa_commit();
    };

    float acc[4][4][4];
#pragma unroll
    for (int i = 0; i < 4; i++)
#pragma unroll
        for (int j = 0; j < 4; j++)
#pragma unroll
            for (int c = 0; c < 4; c++) acc[i][j][c] = 0.0f;

    load_chunk(0);
    load_chunk(1);

    for (int ch = 0; ch < NCH; ch++) {
        if (ch + 1 < NCH) cpa_wait1();
        else              cpa_wait0();
        __syncthreads();
        if (ch + 2 < NCH) load_chunk(ch + 2);

        const __nv_bfloat16* cur = sg + (ch % NSTG) * GSTAGE;
        const __nv_bfloat16* Ahi = cur;
        const __nv_bfloat16* Alo = cur + GTILE;
        const __nv_bfloat16* Bhi = cur + 2 * GTILE;
        const __nv_bfloat16* Blo = cur + 3 * GTILE;

#pragma unroll
        for (int kk = 0; kk < 4; kk++) {
            uint32_t ahi[4][4], alo[4][4], bhi[2][4], blo[2][4];
            const int ar = wm * 64 + (lane & 15);
            const int ak = kk * 16 + (lane >> 4) * 8;
#pragma unroll
            for (int mi = 0; mi < 4; mi++) {
                ldmat_x4(ahi[mi], saddr(Ahi + (ar + mi * 16) * GST + ak));
                ldmat_x4(alo[mi], saddr(Alo + (ar + mi * 16) * GST + ak));
            }
            const int br = wn * 32 + ((lane >> 4) & 1) * 8 + (lane & 7);
            const int bk = kk * 16 + ((lane >> 3) & 1) * 8;
#pragma unroll
            for (int p = 0; p < 2; p++) {
                ldmat_x4(bhi[p], saddr(Bhi + (br + p * 16) * GST + bk));
                ldmat_x4(blo[p], saddr(Blo + (br + p * 16) * GST + bk));
            }
#pragma unroll
            for (int mi = 0; mi < 4; mi++)
#pragma unroll
                for (int ni = 0; ni < 4; ni++) {
                    const uint32_t* bh = &bhi[ni >> 1][(ni & 1) * 2];
                    mma16816(acc[mi][ni], ahi[mi], bh[0], bh[1]);
                }
#pragma unroll
            for (int mi = 0; mi < 4; mi++)
#pragma unroll
                for (int ni = 0; ni < 4; ni++) {
                    const uint32_t* bl = &blo[ni >> 1][(ni & 1) * 2];
                    mma16816(acc[mi][ni], ahi[mi], bl[0], bl[1]);
                }
#pragma unroll
            for (int mi = 0; mi < 4; mi++)
#pragma unroll
                for (int ni = 0; ni < 4; ni++) {
                    const uint32_t* bh = &bhi[ni >> 1][(ni & 1) * 2];
                    mma16816(acc[mi][ni], alo[mi], bh[0], bh[1]);
                }
        }
    }

#pragma unroll
    for (int mi = 0; mi < 4; mi++)
#pragma unroll
        for (int ni = 0; ni < 4; ni++) {
            const int r0 = m0 + wm * 64 + mi * 16 + (lane >> 2);
            const int c0 = n0 + wn * 32 + ni * 8 + (lane & 3) * 2;
            *(float2*)(C + (size_t)r0 * 1024 + c0) =
                make_float2(acc[mi][ni][0], acc[mi][ni][1]);
            *(float2*)(C + (size_t)(r0 + 8) * 1024 + c0) =
                make_float2(acc[mi][ni][2], acc[mi][ni][3]);
        }
}

// ---------------------------------------------------------------------------
// RoPE + split to bf16 hi/lo
// ---------------------------------------------------------------------------
__global__ void rope_split(const float* __restrict__ p5,
                           __nv_bfloat16* __restrict__ qh,  __nv_bfloat16* __restrict__ ql,
                           __nv_bfloat16* __restrict__ kh,  __nv_bfloat16* __restrict__ kl,
                           __nv_bfloat16* __restrict__ q2h, __nv_bfloat16* __restrict__ q2l,
                           __nv_bfloat16* __restrict__ k2h, __nv_bfloat16* __restrict__ k2l,
                           __nv_bfloat16* __restrict__ vh,  __nv_bfloat16* __restrict__ vl) {
    const int idx = blockIdx.x * blockDim.x + threadIdx.x;
    const int i = idx & 31;
    const int h = (idx >> 5) & (HH - 1);
    const int t = (idx >> 9) & (TT - 1);
    const int b = idx >> 20;

    const float inv_freq = powf(10000.0f, -(float)i * (1.0f / 32.0f));
    float c, s;
    sincosf((float)t * inv_freq, &s, &c);

    const size_t base = ((size_t)(b * TT + t)) * DD + h * DH + i;

    __nv_bfloat16* oh[4] = {qh, kh, q2h, k2h};
    __nv_bfloat16* ol[4] = {ql, kl, q2l, k2l};
#pragma unroll
    for (int a = 0; a < 4; a++) {
        const float* in = p5 + (size_t)a * MM * DD;
        float x1 = in[base];
        float x2 = in[base + 32];
        float y1 = fmaf(x1, c, x2 * s);
        float y2 = fmaf(-x1, s, x2 * c);
        unsigned short hh, lll;
        fsplit(y1, hh, lll);
        oh[a][base]      = __ushort_as_bfloat16(hh);
        ol[a][base]      = __ushort_as_bfloat16(lll);
        fsplit(y2, hh, lll);
        oh[a][base + 32] = __ushort_as_bfloat16(hh);
        ol[a][base + 32] = __ushort_as_bfloat16(lll);
    }
    {
        const float* vv = p5 + (size_t)4 * MM * DD;
        unsigned short hh, lll;
        fsplit(vv[base], hh, lll);
        vh[base]      = __ushort_as_bfloat16(hh);
        vl[base]      = __ushort_as_bfloat16(lll);
        fsplit(vv[base + 32], hh, lll);
        vh[base + 32] = __ushort_as_bfloat16(hh);
        vl[base + 32] = __ushort_as_bfloat16(lll);
    }
}

// ---------------------------------------------------------------------------
// Tensor-core causal bilinear attention.
// V now loaded via cp.async (natural [kv][d]) and consumed with ldmatrix.trans.
// ---------------------------------------------------------------------------
__global__ void __launch_bounds__(256, 1) attn_mma(
        const __nv_bfloat16* __restrict__ qh,  const __nv_bfloat16* __restrict__ ql,
        const __nv_bfloat16* __restrict__ q2h, const __nv_bfloat16* __restrict__ q2l,
        const __nv_bfloat16* __restrict__ kh,  const __nv_bfloat16* __restrict__ kl,
        const __nv_bfloat16* __restrict__ k2h, const __nv_bfloat16* __restrict__ k2l,
        const __nv_bfloat16* __restrict__ vh,  const __nv_bfloat16* __restrict__ vl,
        __nv_bfloat16* __restrict__ zh, __nv_bfloat16* __restrict__ zl) {
    extern __shared__ __nv_bfloat16 sb2[];
    const int tid  = threadIdx.x;
    const int lane = tid & 31;
    const int w    = tid >> 5;
    const int qb = (int)gridDim.x - 1 - (int)blockIdx.x;
    const int q0 = qb * 128;
    const int b  = blockIdx.y >> 4;
    const int h  = blockIdx.y & 15;
    const size_t bh_off = (size_t)b * TT * DD + h * DH;

    {
        const __nv_bfloat16* src[4] = {qh, ql, q2h, q2l};
#pragma unroll
        for (int a = 0; a < 4; a++) {
            __nv_bfloat16* dst = sb2 + a * 128 * KST;
            for (int i = tid; i < 1024; i += 256) {
                const int r = i >> 3, ck = (i & 7) * 8;
                cpa16(dst + r * KST + ck, src[a] + bh_off + (size_t)(q0 + r) * DD + ck);
            }
        }
        cpa_commit();
        cpa_wait0();
        __syncthreads();
    }

    uint32_t fqh[4][4], fql[4][4], fq2h[4][4], fq2l[4][4];
    {
        const int ar = w * 16 + (lane & 15);
        const int ak = (lane >> 4) * 8;
#pragma unroll
        for (int kf = 0; kf < 4; kf++) {
            ldmat_x4(fqh [kf], saddr(sb2 + 0 * 128 * KST + ar * KST + kf * 16 + ak));
            ldmat_x4(fql [kf], saddr(sb2 + 1 * 128 * KST + ar * KST + kf * 16 + ak));
            ldmat_x4(fq2h[kf], saddr(sb2 + 2 * 128 * KST + ar * KST + kf * 16 + ak));
            ldmat_x4(fq2l[kf], saddr(sb2 + 3 * 128 * KST + ar * KST + kf * 16 + ak));
        }
    }
    __syncthreads();

    float zacc[8][4];
#pragma unroll
    for (int i = 0; i < 8; i++)
#pragma unroll
        for (int j = 0; j < 4; j++) zacc[i][j] = 0.0f;

    const int nkv = 2 * qb + 2;
    const int br = (lane & 7) + ((lane >> 4) & 1) * 8;
    const int bk = ((lane >> 3) & 1) * 8;
    const float invd2 = 1.0f / ((float)DH * (float)DH);

    // all six tiles (K,K2 hi/lo + V hi/lo natural layout) via cp.async
    auto load_tile = [&](int kj, int buf) {
        __nv_bfloat16* base = sb2 + buf * STAGE;
        const int kv0 = kj * 64;
        const __nv_bfloat16* src[6] = {kh, kl, k2h, k2l, vh, vl};
#pragma unroll
        for (int a = 0; a < 6; a++) {
            __nv_bfloat16* dst = base + a * ATILE;
            for (int i = tid; i < 512; i += 256) {
                const int r = i >> 3, ck = (i & 7) * 8;
                cpa16(dst + r * KST + ck, src[a] + bh_off + (size_t)(kv0 + r) * DD + ck);
            }
        }
    };

    load_tile(0, 0);
    cpa_commit();

    for (int kj = 0; kj < nkv; kj++) {
        cpa_wait0();
        __syncthreads();
        if (kj + 1 < nkv) {
            load_tile(kj + 1, (kj + 1) & 1);
            cpa_commit();
        }

        const __nv_bfloat16* base = sb2 + (kj & 1) * STAGE;
        const int kv0 = kj * 64;
        const bool masked = (kv0 >= q0);

        uint32_t ph[8][2], pl[8][2];
#pragma unroll
        for (int g = 0; g < 4; g++) {
            float s1f[2][4], s2f[2][4];
#pragma unroll
            for (int p = 0; p < 2; p++)
#pragma unroll
                for (int e = 0; e < 4; e++) { s1f[p][e] = 0.0f; s2f[p][e] = 0.0f; }

#pragma unroll
            for (int kf = 0; kf < 4; kf++) {
                uint32_t kh_[4], kl_[4], k2h_[4], k2l_[4];
                const int off = (g * 16 + br) * KST + kf * 16 + bk;
                ldmat_x4(kh_,  saddr(base + 0 * ATILE + off));
                ldmat_x4(kl_,  saddr(base + 1 * ATILE + off));
                ldmat_x4(k2h_, saddr(base + 2 * ATILE + off));
                ldmat_x4(k2l_, saddr(base + 3 * ATILE + off));
#pragma unroll
                for (int p = 0; p < 2; p++) {
                    mma16816(s1f[p], fqh[kf],  kh_[p*2],  kh_[p*2+1]);
                    mma16816(s2f[p], fq2h[kf], k2h_[p*2], k2h_[p*2+1]);
                }
#pragma unroll
                for (int p = 0; p < 2; p++) {
                    mma16816(s1f[p], fqh[kf],  kl_[p*2],  kl_[p*2+1]);
                    mma16816(s2f[p], fq2h[kf], k2l_[p*2], k2l_[p*2+1]);
                }
#pragma unroll
                for (int p = 0; p < 2; p++) {
                    mma16816(s1f[p], fql[kf],  kh_[p*2],  kh_[p*2+1]);
                    mma16816(s2f[p], fq2l[kf], k2h_[p*2], k2h_[p*2+1]);
                }
            }
#pragma unroll
            for (int p = 0; p < 2; p++) {
                const int j = g * 2 + p;
                float pr[4];
#pragma unroll
                for (int e = 0; e < 4; e++) pr[e] = s1f[p][e] * s2f[p][e] * invd2;
                if (masked) {
                    const int qr = q0 + w * 16 + (lane >> 2);
                    const int kc = kv0 + j * 8 + (lane & 3) * 2;
                    if (kc     > qr)     pr[0] = 0.0f;
                    if (kc + 1 > qr)     pr[1] = 0.0f;
                    if (kc     > qr + 8) pr[2] = 0.0f;
                    if (kc + 1 > qr + 8) pr[3] = 0.0f;
                }
                unsigned short hh[4], ll[4];
#pragma unroll
                for (int e = 0; e < 4; e++) fsplit(pr[e], hh[e], ll[e]);
                ph[j][0] = (uint32_t)hh[1] << 16 | hh[0];
                ph[j][1] = (uint32_t)hh[3] << 16 | hh[2];
                pl[j][0] = (uint32_t)ll[1] << 16 | ll[0];
                pl[j][1] = (uint32_t)ll[3] << 16 | ll[2];
            }
        }

        // PV: V fragments via ldmatrix.trans from natural [kv][d] tiles.
        // Row = kv (k-dim of mma), col = d (n-dim). Block order matches
        // non-trans consumption: regs [0],[1] = n-half 0; [2],[3] = n-half 1.
        const int vr_lane = ((lane >> 3) & 1) * 8 + (lane & 7);   // k sub-row
        const int vc_lane = ((lane >> 4) & 1) * 8;                // n sub-col
#pragma unroll
        for (int f = 0; f < 4; f++) {
            uint32_t ah[4] = {ph[2*f][0], ph[2*f][1], ph[2*f+1][0], ph[2*f+1][1]};
            uint32_t al[4] = {pl[2*f][0], pl[2*f][1], pl[2*f+1][0], pl[2*f+1][1]};
            uint32_t vh_[4][4], vl_[4][4];
#pragma unroll
            for (int gd = 0; gd < 4; gd++) {
                const int off = (f * 16 + vr_lane) * KST + gd * 16 + vc_lane;
                ldmat_x4_trans(vh_[gd], saddr(base + 4 * ATILE + off));
                ldmat_x4_trans(vl_[gd], saddr(base + 5 * ATILE + off));
            }
#pragma unroll
            for (int gd = 0; gd < 4; gd++)
#pragma unroll
                for (int p = 0; p < 2; p++)
                    mma16816(zacc[gd*2+p], ah, vh_[gd][p*2], vh_[gd][p*2+1]);
#pragma unroll
            for (int gd = 0; gd < 4; gd++)
#pragma unroll
                for (int p = 0; p < 2; p++)
                    mma16816(zacc[gd*2+p], ah, vl_[gd][p*2], vl_[gd][p*2+1]);
#pragma unroll
            for (int gd = 0; gd < 4; gd++)
#pragma unroll
                for (int p = 0; p < 2; p++)
                    mma16816(zacc[gd*2+p], al, vh_[gd][p*2], vh_[gd][p*2+1]);
        }
    }

    {
        const int r = q0 + w * 16 + (lane >> 2);
        const int c = (lane & 3) * 2;
#pragma unroll
        for (int nd = 0; nd < 8; nd++) {
            unsigned short h0, l0, h1, l1;
#pragma unroll
            for (int half = 0; half < 2; half++) {
                fsplit(zacc[nd][half * 2 + 0], h0, l0);
                fsplit(zacc[nd][half * 2 + 1], h1, l1);
                const size_t off = bh_off + (size_t)(r + half * 8) * DD + nd * 8 + c;
                *(uint32_t*)(zh + off) = (uint32_t)h1 << 16 | h0;
                *(uint32_t*)(zl + off) = (uint32_t)l1 << 16 | l0;
            }
        }
    }
}

// ---------------------------------------------------------------------------
extern "C" void kernel_launch(void* const* d_in, const int* in_sizes, int n_in,
                              void* d_out, int out_size) {
    const float* x     = (const float*)d_in[0];
    const float* Wq    = (const float*)d_in[1];
    const float* Wk    = (const float*)d_in[2];
    const float* Wq2   = (const float*)d_in[3];
    const float* Wk2   = (const float*)d_in[4];
    const float* Wv    = (const float*)d_in[5];
    const float* Wproj = (const float*)d_in[6];
    float* out = (float*)d_out;

    float* p5;
    cudaGetSymbolAddress((void**)&p5, g_p5);

    __nv_bfloat16 *xh, *xl, *zh, *zl, *w6h, *w6l;
    cudaGetSymbolAddress((void**)&xh,  g_xh);  cudaGetSymbolAddress((void**)&xl,  g_xl);
    cudaGetSymbolAddress((void**)&zh,  g_zh);  cudaGetSymbolAddress((void**)&zl,  g_zl);
    cudaGetSymbolAddress((void**)&w6h, g_w6h); cudaGetSymbolAddress((void**)&w6l, g_w6l);

    __nv_bfloat16 *qh, *ql, *q2h, *q2l, *kh, *kl, *k2h, *k2l, *vh, *vl;
    cudaGetSymbolAddress((void**)&qh,  g_qh);  cudaGetSymbolAddress((void**)&ql,  g_ql);
    cudaGetSymbolAddress((void**)&q2h, g_q2h); cudaGetSymbolAddress((void**)&q2l, g_q2l);
    cudaGetSymbolAddress((void**)&kh,  g_kh);  cudaGetSymbolAddress((void**)&kl,  g_kl);
    cudaGetSymbolAddress((void**)&k2h, g_k2h); cudaGetSymbolAddress((void**)&k2l, g_k2l);
    cudaGetSymbolAddress((void**)&vh,  g_vh);  cudaGetSymbolAddress((void**)&vl,  g_vl);

    cudaFuncSetAttribute(gemm_bf16,
                         cudaFuncAttributeMaxDynamicSharedMemorySize, GEMM_SMEM);

    // 1) split inputs
    split_f32<<<MM * DD / 1024, 256>>>(x, xh, xl);
    split_w6<<<dim3(DD * DD / 1024, 6), 256>>>(Wq, Wk, Wq2, Wk2, Wv, Wproj, w6h, w6l);

    // 2) five fused projections
    gemm_bf16<<<dim3(DD / 128, MM / 128, 5), 256, GEMM_SMEM>>>(xh, xl, w6h, w6l, p5);

    // 3) rope + split
    rope_split<<<(BB * TT * HH * 32) / 256, 256>>>(p5, qh, ql, kh, kl,
                                                   q2h, q2l, k2h, k2l, vh, vl);

    // 4) attention (writes zh/zl directly)
    const int attn_smem = 2 * STAGE * (int)sizeof(__nv_bfloat16);
    cudaFuncSetAttribute(attn_mma,
                         cudaFuncAttributeMaxDynamicSharedMemorySize, attn_smem);
    attn_mma<<<dim3(TT / 128, BB * HH), 256, attn_smem>>>(
        qh, ql, q2h, q2l, kh, kl, k2h, k2l, vh, vl, zh, zl);

    // 5) output projection
    gemm_bf16<<<dim3(DD / 128, MM / 128, 1), 256, GEMM_SMEM>>>(
        zh, zl, w6h + (size_t)5 * DD * DD, w6l + (size_t)5 * DD * DD, out);
}